// round 14
// baseline (speedup 1.0000x reference)
#include <cuda_runtime.h>
#include <cuda_bf16.h>
#include <math.h>
#include <stdint.h>

#define BB 8
#define WW 20
#define MM 2048
#define HSCD 16
#define HID 32
#define NHH 32
#define DG 80
#define SPCAP 96

// ---------------- scratch (device globals; no allocations) ----------------
__device__ float g_hSC[BB*MM*HSCD];
__device__ float g_kpart[BB*8*1056];
__device__ float g_gram[BB*1024];
__device__ float g_ksum[BB*32];
__device__ float g_hT[BB*MM*NHH];
__device__ float g_t[BB*MM];
__device__ float g_cgp[16*BB*MM];
__device__ float g_c[BB*MM];
__device__ float g_tc[BB*MM];
__device__ float g_spv[MM*SPCAP];
__device__ int   g_spi[MM*SPCAP];
__device__ int   g_spc[MM];
__device__ float g_dinv[BB*MM];
__device__ float g_node0[BB*MM*DG];
__device__ float g_node1[BB*MM*DG];
__device__ float g_node2[BB*MM*DG];
__device__ float g_u[BB*DG];
// bf16 split operands
__device__ __nv_bfloat16 g_adjh[(size_t)MM*MM];
__device__ __nv_bfloat16 g_adjl[(size_t)MM*MM];
__device__ __nv_bfloat16 g_Bh[(size_t)BB*DG*MM];
__device__ __nv_bfloat16 g_Bl[(size_t)BB*DG*MM];

__device__ __forceinline__ float sigf(float x){ return 1.f/(1.f+expf(-x)); }
__device__ __forceinline__ float eluf(float x){ return x>0.f ? x : expf(x)-1.f; }
__device__ __forceinline__ float fsig(float x){ return __fdividef(1.f, 1.f + __expf(-x)); }
__device__ __forceinline__ float ftanh(float x){ return 1.f - 2.f*__fdividef(1.f, 1.f + __expf(2.f*x)); }
__device__ __forceinline__ float felu(float x){ return x>0.f ? x : __expf(x)-1.f; }

#define FFMA2(acc, a, b) asm("fma.rn.f32x2 %0, %1, %2, %0;" : "+l"(acc) : "l"(a), "l"(b))
#define PACK2(p, lo, hi) asm("mov.b64 %0, {%1, %2};" : "=l"(p) : "f"(lo), "f"(hi))
#define PACKB(p, v)      asm("mov.b64 %0, {%1, %1};" : "=l"(p) : "f"(v))
#define UNPACK2(lo, hi, p) asm("mov.b64 {%0, %1}, %2;" : "=f"(lo), "=f"(hi) : "l"(p))

#define MMA16816(d, a0,a1,a2,a3, b0,b1) \
    asm volatile("mma.sync.aligned.m16n8k16.row.col.f32.bf16.bf16.f32 " \
        "{%0,%1,%2,%3}, {%4,%5,%6,%7}, {%8,%9}, {%0,%1,%2,%3};" \
        : "+f"((d)[0]), "+f"((d)[1]), "+f"((d)[2]), "+f"((d)[3]) \
        : "r"(a0), "r"(a1), "r"(a2), "r"(a3), "r"(b0), "r"(b1))

#define LDSM_X4(r0,r1,r2,r3, addr) \
    asm volatile("ldmatrix.sync.aligned.m8n8.x4.shared.b16 {%0,%1,%2,%3}, [%4];" \
        : "=r"(r0), "=r"(r1), "=r"(r2), "=r"(r3) : "r"(addr))
#define LDSM_X2(r0,r1, addr) \
    asm volatile("ldmatrix.sync.aligned.m8n8.x2.shared.b16 {%0,%1}, [%2];" \
        : "=r"(r0), "=r"(r1) : "r"(addr))

__device__ __forceinline__ uint32_t smem_u32(const void* p){
    uint32_t a;
    asm("{ .reg .u64 t; cvta.to.shared.u64 t, %1; cvt.u32.u64 %0, t; }" : "=r"(a) : "l"(p));
    return a;
}

// ---------------- 1) h_SC ----------------
__global__ void k_hsc(const float* __restrict__ x, const float* __restrict__ Wt,
                      const float* __restrict__ bt){
    __shared__ float xs[WW*256];
    __shared__ float sWt[WW*HSCD];
    __shared__ float sbt[HSCD];
    int b = blockIdx.x, mt = blockIdx.y, tid = threadIdx.x;
    int m0 = mt*256;
    #pragma unroll
    for (int w = 0; w < WW; ++w) xs[w*256+tid] = x[(b*WW+w)*MM + m0 + tid];
    for (int i = tid; i < WW*HSCD; i += 256) sWt[i] = Wt[i];
    if (tid < HSCD) sbt[tid] = bt[tid];
    __syncthreads();
    float hv[HSCD];
    #pragma unroll
    for (int k = 0; k < HSCD; ++k) hv[k] = sbt[k];
    #pragma unroll
    for (int w = 0; w < WW; ++w){
        float xv = xs[w*256+tid];
        #pragma unroll
        for (int k = 0; k < HSCD; ++k) hv[k] = fmaf(xv, sWt[w*HSCD+k], hv[k]);
    }
    float* op = &g_hSC[(size_t)(b*MM + m0 + tid)*HSCD];
    #pragma unroll
    for (int k = 0; k < HSCD; ++k) op[k] = hv[k];
}

// ---------------- 2) key sum + Gram partials ----------------
__global__ void k_kstats(const float* __restrict__ WKw, const float* __restrict__ WKb){
    __shared__ float sW[HSCD*HID + HID];
    __shared__ float Ks[256*33];
    int b = blockIdx.x, ch = blockIdx.y, tid = threadIdx.x;
    for (int i = tid; i < HSCD*HID + HID; i += 256)
        sW[i] = (i < HSCD*HID) ? WKw[i] : WKb[i - HSCD*HID];
    __syncthreads();
    int m = ch*256 + tid;
    const float* hp = &g_hSC[(size_t)(b*MM+m)*HSCD];
    float hc[HSCD];
    #pragma unroll
    for (int c = 0; c < HSCD; ++c) hc[c] = hp[c];
    #pragma unroll
    for (int h = 0; h < HID; ++h){
        float a = sW[HSCD*HID + h];
        #pragma unroll
        for (int c = 0; c < HSCD; ++c) a = fmaf(hc[c], sW[c*HID+h], a);
        Ks[tid*33 + h] = a;
    }
    __syncthreads();
    float* outp = &g_kpart[(size_t)(b*8 + ch)*1056];
    #pragma unroll
    for (int e = 0; e < 4; ++e){
        int idx = tid*4 + e, i = idx >> 5, j = idx & 31;
        float s = 0.f;
        for (int r = 0; r < 256; ++r) s = fmaf(Ks[r*33+i], Ks[r*33+j], s);
        outp[idx] = s;
    }
    if (tid < 32){
        float s = 0.f;
        for (int r = 0; r < 256; ++r) s += Ks[r*33+tid];
        outp[1024+tid] = s;
    }
}

__global__ void k_kreduce(){
    int b = blockIdx.x, tid = threadIdx.x;
    for (int idx = tid; idx < 1056; idx += 256){
        float s = 0.f;
        #pragma unroll
        for (int c = 0; c < 8; ++c) s += g_kpart[(size_t)(b*8+c)*1056 + idx];
        if (idx < 1024) g_gram[b*1024+idx] = s;
        else            g_ksum[b*32 + idx - 1024] = s;
    }
}

// ---------------- 4+5) GRU fused with score ----------------
__global__ void __launch_bounds__(256,2) k_gru(const float* __restrict__ x, const float* __restrict__ wih,
                      const float* __restrict__ whh, const float* __restrict__ bih,
                      const float* __restrict__ bhh,
                      const float* __restrict__ W1, const float* __restrict__ W2,
                      const float* __restrict__ b1, const float* __restrict__ V,
                      const float* __restrict__ bv){
    __shared__ float sW12[512];
    __shared__ float sV[16], sb1[16];
    __shared__ __align__(16) float sH[8*32];
    int tid = threadIdx.x, lane = tid & 31, wid = tid >> 5;
    for (int i = tid; i < 512; i += 256) sW12[i] = W1[i] + W2[i];
    if (tid < 16){ sV[tid] = V[tid]; sb1[tid] = b1[tid]; }
    __syncthreads();
    int seq = blockIdx.x*8 + wid;
    int b = seq >> 11, m = seq & 2047;
    const float4* pr = (const float4*)&whh[lane*32];
    const float4* pz = (const float4*)&whh[(lane+32)*32];
    const float4* pn = (const float4*)&whh[(lane+64)*32];
    unsigned long long prz[32];
    float wn[32];
    #pragma unroll
    for (int k = 0; k < 8; ++k){
        float4 r4 = pr[k], z4 = pz[k], n4 = pn[k];
        PACK2(prz[k*4+0], r4.x, z4.x);
        PACK2(prz[k*4+1], r4.y, z4.y);
        PACK2(prz[k*4+2], r4.z, z4.z);
        PACK2(prz[k*4+3], r4.w, z4.w);
        wn[k*4+0] = n4.x; wn[k*4+1] = n4.y; wn[k*4+2] = n4.z; wn[k*4+3] = n4.w;
    }
    float wxr = wih[lane], wxz = wih[32+lane], wxn = wih[64+lane];
    float bxr = bih[lane], bxz = bih[32+lane], bxn = bih[64+lane];
    unsigned long long brz; PACK2(brz, bhh[lane], bhh[32+lane]);
    float bn = bhh[64+lane];
    float xv = (lane < WW) ? x[(b*WW+lane)*MM + m] : 0.f;
    float* myH = &sH[wid*32];
    float h = 0.f;
    for (int t = 0; t < WW; ++t){
        float xt = __shfl_sync(0xffffffffu, xv, t);
        myH[lane] = h;
        __syncwarp();
        unsigned long long arz = brz;
        float an = bn;
        #pragma unroll
        for (int k = 0; k < 8; ++k){
            float4 h4 = *(const float4*)&myH[k*4];
            unsigned long long p0, p1, p2, p3;
            PACKB(p0, h4.x); PACKB(p1, h4.y); PACKB(p2, h4.z); PACKB(p3, h4.w);
            FFMA2(arz, prz[k*4+0], p0);
            FFMA2(arz, prz[k*4+1], p1);
            FFMA2(arz, prz[k*4+2], p2);
            FFMA2(arz, prz[k*4+3], p3);
            an = fmaf(wn[k*4+0], h4.x, an);
            an = fmaf(wn[k*4+1], h4.y, an);
            an = fmaf(wn[k*4+2], h4.z, an);
            an = fmaf(wn[k*4+3], h4.w, an);
        }
        __syncwarp();
        float ar, az; UNPACK2(ar, az, arz);
        float r = fsig(fmaf(xt, wxr, bxr) + ar);
        float z = fsig(fmaf(xt, wxz, bxz) + az);
        float n = ftanh(fmaf(xt, wxn, bxn) + r*an);
        h = (1.f - z)*n + z*h;
    }
    g_hT[(size_t)seq*32 + lane] = h;
    myH[lane] = h;
    __syncwarp();
    float ao = (lane < 16) ? sb1[lane] : 0.f;
    #pragma unroll
    for (int k = 0; k < 8; ++k){
        float4 h4 = *(const float4*)&myH[k*4];
        const float* wrow = &sW12[(lane & 15)*32 + k*4];
        ao = fmaf(h4.x, wrow[0], ao);
        ao = fmaf(h4.y, wrow[1], ao);
        ao = fmaf(h4.z, wrow[2], ao);
        ao = fmaf(h4.w, wrow[3], ao);
    }
    float so = (lane < 16) ? felu(ao)*sV[lane] : 0.f;
    #pragma unroll
    for (int o = 8; o; o >>= 1) so += __shfl_down_sync(0xffffffffu, so, o);
    if (lane == 0){
        float s = so + bv[0];
        g_t[seq] = s / fmaxf(fabsf(s)*45.254833995939045f, 1e-12f);
    }
}

// ---------------- 3+9) rownorm fused with node0 build ----------------
__global__ void k_rownorm(const float* __restrict__ WQw, const float* __restrict__ WQb,
                          const float* __restrict__ tenc_w, const float* __restrict__ tenc_b,
                          const float* __restrict__ senc_w, const float* __restrict__ senc_b,
                          const float* __restrict__ degree){
    __shared__ float sW[HSCD*HID];
    __shared__ float sb[HID];
    __shared__ float sG[1024];
    __shared__ float sk[32];
    __shared__ float senc[4*32];
    int b = blockIdx.x, tid = threadIdx.x;
    for (int i = tid; i < HSCD*HID; i += 256) sW[i] = WQw[i];
    if (tid < HID) sb[tid] = WQb[tid];
    for (int i = tid; i < 1024; i += 256) sG[i] = g_gram[b*1024+i];
    if (tid < 32) sk[tid] = g_ksum[b*32+tid];
    if (tid < 32){
        senc[tid] = senc_w[tid]; senc[32+tid] = senc_b[tid];
        senc[64+tid] = tenc_w[tid]; senc[96+tid] = tenc_b[tid];
    }
    __syncthreads();
    int m = blockIdx.y*256 + tid;
    const float* hp = &g_hSC[(size_t)(b*MM+m)*HSCD];
    float hc[HSCD];
    #pragma unroll
    for (int c = 0; c < HSCD; ++c) hc[c] = hp[c];
    float q[HID];
    #pragma unroll
    for (int h = 0; h < HID; ++h){
        float a = sb[h];
        #pragma unroll
        for (int c = 0; c < HSCD; ++c) a = fmaf(hc[c], sW[c*HID+h], a);
        q[h] = a;
    }
    float num = 0.f, den = 0.f;
    #pragma unroll
    for (int h = 0; h < HID; ++h) num = fmaf(q[h], sk[h], num);
    #pragma unroll
    for (int i = 0; i < HID; ++i){
        float tmp = 0.f;
        #pragma unroll
        for (int j = 0; j < HID; ++j) tmp = fmaf(sG[i*32+j], q[j], tmp);
        den = fmaf(q[i], tmp, den);
    }
    float rn = num / fmaxf(sqrtf(fmaxf(den, 0.f)), 1e-12f);
    float* np = &g_node0[(size_t)(b*MM+m)*DG];
    #pragma unroll
    for (int c = 0; c < HSCD; ++c) np[c] = hc[c];
    float dm = degree[m];
    #pragma unroll
    for (int h = 0; h < 32; ++h) np[16+h] = fmaf(dm, senc[h], senc[32+h]);
    #pragma unroll
    for (int h = 0; h < 32; ++h) np[48+h] = fmaf(rn, senc[64+h], senc[96+h]);
}

// ---------------- 6) c_gate ----------------
__global__ void k_cg_part(const float* __restrict__ Wb){
    __shared__ float ts[8*128];
    int jt = blockIdx.x, nc = blockIdx.y, tid = threadIdx.x;
    int n0 = nc*128;
    for (int idx = tid; idx < 1024; idx += 256){
        int bb = idx >> 7, nn = idx & 127;
        ts[idx] = g_t[bb*MM + n0 + nn];
    }
    __syncthreads();
    int j = jt*256 + tid;
    float acc[8] = {0,0,0,0,0,0,0,0};
    for (int nn = 0; nn < 128; ++nn){
        float w = Wb[(size_t)(n0+nn)*MM + j];
        #pragma unroll
        for (int bb = 0; bb < 8; ++bb) acc[bb] = fmaf(ts[bb*128+nn], w, acc[bb]);
    }
    #pragma unroll
    for (int bb = 0; bb < 8; ++bb) g_cgp[(size_t)(nc*8+bb)*MM + j] = acc[bb];
}

__global__ void k_cg_fin(const float* __restrict__ wb){
    int gid = blockIdx.x*256 + threadIdx.x;
    int b = gid >> 11, j = gid & 2047;
    float s = wb[0];
    #pragma unroll
    for (int nc = 0; nc < 16; ++nc) s += g_cgp[(size_t)(nc*8+b)*MM + j];
    float c = sigf(s);
    g_c[gid] = c;
    g_tc[gid] = g_t[gid]*(1.f - c);
}

// ---------------- 7) sparse spatial ----------------
__global__ void k_spatial(const float* __restrict__ d_gate, const float* __restrict__ adj_orig,
                          const float* __restrict__ degree){
    int tid = threadIdx.x, lane = tid & 31, wid = tid >> 5;
    int i = blockIdx.x*8 + wid;
    float di = degree[i];
    int cnt = 0;
    for (int j0 = 0; j0 < MM; j0 += 32){
        int j = j0 + lane;
        float a = adj_orig[(size_t)i*MM + j];
        bool nz = a > 0.f;
        unsigned mask = __ballot_sync(0xffffffffu, nz);
        if (nz){
            float v = a * sigf(d_gate[(size_t)i*MM + j]*di*degree[j]);
            int pos = cnt + __popc(mask & ((1u << lane) - 1u));
            if (pos < SPCAP){ g_spi[i*SPCAP+pos] = j; g_spv[i*SPCAP+pos] = v; }
        }
        cnt += __popc(mask);
    }
    if (lane == 0) g_spc[i] = min(cnt, SPCAP);
}

// ---------------- 8) degree counts ----------------
__global__ void k_deg(const float* __restrict__ adj_geo){
    __shared__ float cs[8*512];
    __shared__ float tcs[8*512];
    int tid = threadIdx.x, lane = tid & 31, w = tid >> 5;
    int i = blockIdx.x*8 + w;
    int cnt[8] = {0,0,0,0,0,0,0,0};
    for (int j0 = 0; j0 < MM; j0 += 512){
        __syncthreads();
        for (int idx = tid; idx < 4096; idx += 256){
            int bb = idx >> 9, jj = idx & 511;
            cs[idx]  = g_c[bb*MM + j0 + jj];
            tcs[idx] = g_tc[bb*MM + j0 + jj];
        }
        __syncthreads();
        for (int j = lane; j < 512; j += 32){
            float ag = adj_geo[(size_t)i*MM + j0 + j];
            #pragma unroll
            for (int bb = 0; bb < 8; ++bb){
                float dyn = fmaf(ag, cs[bb*512+j], tcs[bb*512+j]);
                cnt[bb] += (dyn > 0.f);
            }
        }
    }
    int sc = g_spc[i];
    for (int s = lane; s < sc; s += 32){
        int j = g_spi[i*SPCAP+s]; float v = g_spv[i*SPCAP+s];
        float ag = adj_geo[(size_t)i*MM + j];
        #pragma unroll
        for (int bb = 0; bb < 8; ++bb){
            float dyn = fmaf(ag, g_c[bb*MM+j], g_tc[bb*MM+j]);
            if (dyn <= 0.f && dyn + v > 0.f) cnt[bb]++;
        }
    }
    #pragma unroll
    for (int bb = 0; bb < 8; ++bb){
        int vv = cnt[bb];
        #pragma unroll
        for (int o = 16; o; o >>= 1) vv += __shfl_down_sync(0xffffffffu, vv, o);
        if (lane == 0) g_dinv[bb*MM + i] = (vv > 0) ? 1.f/(float)vv : 0.f;
    }
}

// ---------------- 10) rank-1 term u ----------------
__global__ void k_u(const float* __restrict__ node){
    __shared__ float red[256];
    int b = blockIdx.x, d = blockIdx.y, tid = threadIdx.x;
    float a = 0.f;
    for (int j = tid; j < MM; j += 256)
        a = fmaf(g_tc[b*MM+j], node[(size_t)(b*MM+j)*DG + d], a);
    red[tid] = a; __syncthreads();
    for (int s = 128; s; s >>= 1){ if (tid < s) red[tid] += red[tid+s]; __syncthreads(); }
    if (tid == 0) g_u[b*DG + d] = red[0];
}

// ---------------- adj -> bf16 hi/lo (once) ----------------
__global__ void k_adjcvt(const float* __restrict__ adj){
    size_t idx = (size_t)blockIdx.x*256 + threadIdx.x;   // over 2M float2
    float2 v = ((const float2*)adj)[idx];
    __nv_bfloat162 h2 = __floats2bfloat162_rn(v.x, v.y);
    float hx = __bfloat162float(__low2bfloat16(h2));
    float hy = __bfloat162float(__high2bfloat16(h2));
    __nv_bfloat162 l2 = __floats2bfloat162_rn(v.x - hx, v.y - hy);
    *(__nv_bfloat162*)&g_adjh[idx*2] = h2;
    *(__nv_bfloat162*)&g_adjl[idx*2] = l2;
}

// ---------------- B matrix build: B[b][d][j] = c_j * node[j][d] (bf16 hi/lo) ----------------
__global__ void k_bmat(const float* __restrict__ node){
    __shared__ float sT[64*DG];
    int j0 = blockIdx.x*64, b = blockIdx.y, tid = threadIdx.x;
    for (int idx = tid; idx < 64*DG; idx += 256){
        int j = idx/DG, d = idx%DG;
        sT[idx] = g_c[b*MM + j0 + j] * node[(size_t)(b*MM + j0 + j)*DG + d];
    }
    __syncthreads();
    for (int idx = tid; idx < 64*DG; idx += 256){
        int d = idx >> 6, jj = idx & 63;
        float v = sT[jj*DG + d];
        __nv_bfloat16 h = __float2bfloat16(v);
        __nv_bfloat16 l = __float2bfloat16(v - __bfloat162float(h));
        size_t o = (size_t)(b*DG + d)*MM + j0 + jj;
        g_Bh[o] = h; g_Bl[o] = l;
    }
}

// ---------------- 11) fused GNN layer: mma.sync bf16 split, 512 threads ----------------
// warps: m-group = wid>>1 (16 rows), n-half = wid&1 (40 cols = 5 n8-tiles)
__global__ void __launch_bounds__(512,1) k_gemm(const float* __restrict__ nodeIn, float* __restrict__ nodeOut,
                       const float* __restrict__ gw, const float* __restrict__ gb){
    extern __shared__ char dsm[];
    __nv_bfloat16* sAh = (__nv_bfloat16*)dsm;
    __nv_bfloat16* sAl = (__nv_bfloat16*)(dsm + 18432);
    __nv_bfloat16* sBh = (__nv_bfloat16*)(dsm + 36864);
    __nv_bfloat16* sBl = (__nv_bfloat16*)(dsm + 48384);
    float* sY = (float*)dsm;
    float* sG = (float*)(dsm + 43008);

    int tid = threadIdx.x, lane = tid & 31, wid = tid >> 5;
    int i0 = blockIdx.x*128, b = blockIdx.y;
    int mBase = (wid >> 1)*16, nBase = (wid & 1)*40;
    int gid = lane >> 2, t2 = (lane & 3)*2;

    uint32_t aBase = smem_u32(sAh) + (uint32_t)((mBase + (lane & 15))*144 + (lane >> 4)*16);
    uint32_t bBase = smem_u32(sBh) + (uint32_t)((nBase + (lane & 7))*144 + ((lane >> 3) & 1)*16);

    // prefetch coords: A 128x64 hi/lo via uint4 (1024 slots), B 80x64 via uint4 (640 slots)
    int ra[2], sa[2];
    #pragma unroll
    for (int e = 0; e < 2; ++e){ int p = tid + e*512; ra[e] = p >> 3; sa[e] = (p & 7)*8; }
    int p1 = tid;
    int db0 = p1 >> 3, sb0 = (p1 & 7)*8;
    int p2 = tid + 512;
    int db1 = p2 >> 3, sb1v = (p2 & 7)*8;
    bool hasB1 = (p2 < 640);

    uint4 pAh[2], pAl[2], pBh0, pBl0, pBh1, pBl1;
    #pragma unroll
    for (int e = 0; e < 2; ++e){
        size_t o = (size_t)(i0 + ra[e])*MM + sa[e];
        pAh[e] = *(const uint4*)&g_adjh[o];
        pAl[e] = *(const uint4*)&g_adjl[o];
    }
    {
        size_t o = (size_t)(b*DG + db0)*MM + sb0;
        pBh0 = *(const uint4*)&g_Bh[o];
        pBl0 = *(const uint4*)&g_Bl[o];
        if (hasB1){
            size_t o1 = (size_t)(b*DG + db1)*MM + sb1v;
            pBh1 = *(const uint4*)&g_Bh[o1];
            pBl1 = *(const uint4*)&g_Bl[o1];
        }
    }

    float acc[5][4];
    #pragma unroll
    for (int n = 0; n < 5; ++n)
        #pragma unroll
        for (int k = 0; k < 4; ++k) acc[n][k] = 0.f;

    for (int jt = 0; jt < 32; ++jt){
        __syncthreads();
        #pragma unroll
        for (int e = 0; e < 2; ++e){
            *(uint4*)&sAh[ra[e]*72 + sa[e]] = pAh[e];
            *(uint4*)&sAl[ra[e]*72 + sa[e]] = pAl[e];
        }
        *(uint4*)&sBh[db0*72 + sb0] = pBh0;
        *(uint4*)&sBl[db0*72 + sb0] = pBl0;
        if (hasB1){
            *(uint4*)&sBh[db1*72 + sb1v] = pBh1;
            *(uint4*)&sBl[db1*72 + sb1v] = pBl1;
        }
        if (jt + 1 < 32){
            int j0 = (jt+1)*64;
            #pragma unroll
            for (int e = 0; e < 2; ++e){
                size_t o = (size_t)(i0 + ra[e])*MM + j0 + sa[e];
                pAh[e] = *(const uint4*)&g_adjh[o];
                pAl[e] = *(const uint4*)&g_adjl[o];
            }
            size_t o = (size_t)(b*DG + db0)*MM + j0 + sb0;
            pBh0 = *(const uint4*)&g_Bh[o];
            pBl0 = *(const uint4*)&g_Bl[o];
            if (hasB1){
                size_t o1 = (size_t)(b*DG + db1)*MM + j0 + sb1v;
                pBh1 = *(const uint4*)&g_Bh[o1];
                pBl1 = *(const uint4*)&g_Bl[o1];
            }
        }
        __syncthreads();
        #pragma unroll
        for (int ks = 0; ks < 4; ++ks){
            uint32_t aA = aBase + ks*32;
            uint32_t ah0, ah1, ah2, ah3, al0, al1, al2, al3;
            LDSM_X4(ah0, ah1, ah2, ah3, aA);
            LDSM_X4(al0, al1, al2, al3, aA + 18432);
            #pragma unroll
            for (int nt = 0; nt < 5; ++nt){
                uint32_t bA = bBase + nt*1152 + ks*32;
                uint32_t bh0, bh1, bl0, bl1;
                LDSM_X2(bh0, bh1, bA);
                LDSM_X2(bl0, bl1, bA + 11520);
                MMA16816(acc[nt], ah0, ah1, ah2, ah3, bh0, bh1);
                MMA16816(acc[nt], ah0, ah1, ah2, ah3, bl0, bl1);
                MMA16816(acc[nt], al0, al1, al2, al3, bh0, bh1);
            }
        }
    }
    __syncthreads();
    // write accumulators to sY
    #pragma unroll
    for (int nt = 0; nt < 5; ++nt){
        int col = nBase + nt*8 + t2;
        sY[(mBase+gid)*84   + col]     = acc[nt][0];
        sY[(mBase+gid)*84   + col + 1] = acc[nt][1];
        sY[(mBase+gid+8)*84 + col]     = acc[nt][2];
        sY[(mBase+gid+8)*84 + col + 1] = acc[nt][3];
    }
    for (int idx = tid; idx < 6400; idx += 512)
        sG[(idx/80)*84 + idx%80] = gw[idx];
    __syncthreads();

    int q = tid & 3, ig = tid >> 2;   // ig in [0,128)
    // ---- pass 1: sparse + rank-1 + deg scaling ----
    {
        int row = ig;
        int i = i0 + row;
        float a20[20];
        float4* yp = (float4*)&sY[row*84 + q*20];
        #pragma unroll
        for (int v = 0; v < 5; ++v){
            float4 y4 = yp[v];
            a20[v*4+0] = y4.x; a20[v*4+1] = y4.y; a20[v*4+2] = y4.z; a20[v*4+3] = y4.w;
        }
        int sc = g_spc[i];
        for (int s = 0; s < sc; ++s){
            int j = g_spi[i*SPCAP+s]; float v = g_spv[i*SPCAP+s];
            const float4* np = (const float4*)&nodeIn[(size_t)(b*MM + j)*DG + q*20];
            #pragma unroll
            for (int vv = 0; vv < 5; ++vv){
                float4 n = np[vv];
                a20[vv*4+0] = fmaf(v, n.x, a20[vv*4+0]);
                a20[vv*4+1] = fmaf(v, n.y, a20[vv*4+1]);
                a20[vv*4+2] = fmaf(v, n.z, a20[vv*4+2]);
                a20[vv*4+3] = fmaf(v, n.w, a20[vv*4+3]);
            }
        }
        float dinv = g_dinv[b*MM + i];
        const float4* up = (const float4*)&g_u[b*DG + q*20];
        #pragma unroll
        for (int vv = 0; vv < 5; ++vv){
            float4 u4 = up[vv];
            float4 y;
            y.x = dinv*(a20[vv*4+0] + u4.x);
            y.y = dinv*(a20[vv*4+1] + u4.y);
            y.z = dinv*(a20[vv*4+2] + u4.z);
            y.w = dinv*(a20[vv*4+3] + u4.w);
            yp[vv] = y;
        }
    }
    __syncthreads();
    // ---- pass 2: z = y @ gw + gb, elu ----
    {
        int i = i0 + ig;
        unsigned long long z2[10];
        const float2* gb2 = (const float2*)&gb[q*20];
        #pragma unroll
        for (int k = 0; k < 10; ++k){ float2 g2 = gb2[k]; PACK2(z2[k], g2.x, g2.y); }
        for (int d = 0; d < 80; ++d){
            float yv = sY[ig*84 + d];
            unsigned long long py; PACKB(py, yv);
            const ulonglong2* gp = (const ulonglong2*)&sG[d*84 + q*20];
            #pragma unroll
            for (int v = 0; v < 5; ++v){
                ulonglong2 g2 = gp[v];
                FFMA2(z2[v*2],   py, g2.x);
                FFMA2(z2[v*2+1], py, g2.y);
            }
        }
        float* op = &nodeOut[(size_t)(b*MM + i)*DG + q*20];
        #pragma unroll
        for (int v = 0; v < 5; ++v){
            float4 o4;
            float za, zbv, zc, zd;
            UNPACK2(za, zbv, z2[v*2]);
            UNPACK2(zc, zd, z2[v*2+1]);
            o4.x = eluf(za); o4.y = eluf(zbv); o4.z = eluf(zc); o4.w = eluf(zd);
            *(float4*)&op[v*4] = o4;
        }
    }
}

// ---------------- 12) final projection ----------------
__global__ void k_final(const float* __restrict__ out_w, const float* __restrict__ out_b,
                        float* __restrict__ out){
    __shared__ float sw[272];
    int tid = threadIdx.x;
    for (int i = tid; i < 272; i += 256) sw[i] = out_w[i];
    __syncthreads();
    int gid = blockIdx.x*256 + tid;
    float a = out_b[0];
    const float* n0 = &g_node0[(size_t)gid*DG];
    const float* n1 = &g_node1[(size_t)gid*DG];
    const float* n2 = &g_node2[(size_t)gid*DG];
    const float* ht = &g_hT[(size_t)gid*32];
    #pragma unroll
    for (int d = 0; d < DG; ++d) a = fmaf(n0[d], sw[d], a);
    #pragma unroll
    for (int d = 0; d < DG; ++d) a = fmaf(n1[d], sw[80+d], a);
    #pragma unroll
    for (int d = 0; d < DG; ++d) a = fmaf(n2[d], sw[160+d], a);
    #pragma unroll
    for (int h = 0; h < 32; ++h) a = fmaf(ht[h], sw[240+h], a);
    out[gid] = a;
}

// ---------------- launch ----------------
extern "C" void kernel_launch(void* const* d_in, const int* in_sizes, int n_in,
                              void* d_out, int out_size){
    const float* x       = (const float*)d_in[0];
    const float* Wt      = (const float*)d_in[1];
    const float* bt      = (const float*)d_in[2];
    const float* WQ_w    = (const float*)d_in[3];
    const float* WQ_b    = (const float*)d_in[4];
    const float* WK_w    = (const float*)d_in[5];
    const float* WK_b    = (const float*)d_in[6];
    const float* tenc_w  = (const float*)d_in[7];
    const float* tenc_b  = (const float*)d_in[8];
    const float* senc_w  = (const float*)d_in[9];
    const float* senc_b  = (const float*)d_in[10];
    const float* gru_wih = (const float*)d_in[11];
    const float* gru_whh = (const float*)d_in[12];
    const float* gru_bih = (const float*)d_in[13];
    const float* gru_bhh = (const float*)d_in[14];
    const float* V       = (const float*)d_in[15];
    const float* bv      = (const float*)d_in[16];
    const float* W1      = (const float*)d_in[17];
    const float* b1      = (const float*)d_in[18];
    const float* W2      = (const float*)d_in[19];
    const float* Wb      = (const float*)d_in[20];
    const float* wb      = (const float*)d_in[21];
    const float* d_gate  = (const float*)d_in[22];
    const float* adj_geo = (const float*)d_in[23];
    const float* adj_orig= (const float*)d_in[24];
    const float* degree  = (const float*)d_in[25];
    const float* gnn_w   = (const float*)d_in[26];
    const float* gnn_b   = (const float*)d_in[27];
    const float* out_w   = (const float*)d_in[28];
    const float* out_b   = (const float*)d_in[29];
    float* out = (float*)d_out;

    const int GEMM_SMEM = 69888;
    cudaFuncSetAttribute(k_gemm, cudaFuncAttributeMaxDynamicSharedMemorySize, GEMM_SMEM);

    float *n0, *n1, *n2;
    cudaGetSymbolAddress((void**)&n0, g_node0);
    cudaGetSymbolAddress((void**)&n1, g_node1);
    cudaGetSymbolAddress((void**)&n2, g_node2);

    k_adjcvt<<<MM*MM/2/256, 256>>>(adj_geo);
    k_hsc<<<dim3(BB, MM/256), 256>>>(x, Wt, bt);
    k_kstats<<<dim3(BB, 8), 256>>>(WK_w, WK_b);
    k_kreduce<<<BB, 256>>>();
    k_gru<<<BB*MM/8, 256>>>(x, gru_wih, gru_whh, gru_bih, gru_bhh,
                            W1, W2, b1, V, bv);
    k_rownorm<<<dim3(BB, MM/256), 256>>>(WQ_w, WQ_b, tenc_w, tenc_b,
                                         senc_w, senc_b, degree);
    k_cg_part<<<dim3(8, 16), 256>>>(Wb);
    k_cg_fin<<<BB*MM/256, 256>>>(wb);
    k_spatial<<<MM/8, 256>>>(d_gate, adj_orig, degree);
    k_deg<<<MM/8, 256>>>(adj_geo);
    k_u<<<dim3(BB, DG), 256>>>(n0);
    k_bmat<<<dim3(MM/64, BB), 256>>>(n0);
    k_gemm<<<dim3(MM/128, BB), 512, GEMM_SMEM>>>(n0, n1, gnn_w, gnn_b);
    k_u<<<dim3(BB, DG), 256>>>(n1);
    k_bmat<<<dim3(MM/64, BB), 256>>>(n1);
    k_gemm<<<dim3(MM/128, BB), 512, GEMM_SMEM>>>(n1, n2, gnn_w + 6400, gnn_b + 80);
    k_final<<<BB*MM/256, 256>>>(out_w, out_b, out);
}

// round 15
// speedup vs baseline: 1.0116x; 1.0116x over previous
#include <cuda_runtime.h>
#include <cuda_bf16.h>
#include <math.h>
#include <stdint.h>

#define BB 8
#define WW 20
#define MM 2048
#define HSCD 16
#define HID 32
#define NHH 32
#define DG 80
#define SPCAP 96

// ---------------- scratch (device globals; no allocations) ----------------
__device__ float g_hSC[BB*MM*HSCD];
__device__ float g_kpart[BB*8*1056];
__device__ float g_gram[BB*1024];
__device__ float g_ksum[BB*32];
__device__ float g_hT[BB*MM*NHH];
__device__ float g_t[BB*MM];
__device__ float g_cgp[16*BB*MM];
__device__ float g_c[BB*MM];
__device__ float g_tc[BB*MM];
__device__ float g_spv[MM*SPCAP];
__device__ int   g_spi[MM*SPCAP];
__device__ int   g_spc[MM];
__device__ float g_dinv[BB*MM];
__device__ float g_node0[BB*MM*DG];
__device__ float g_node1[BB*MM*DG];
__device__ float g_node2[BB*MM*DG];
__device__ float g_upart[BB*32*DG];
// bf16 split operands
__device__ __nv_bfloat16 g_adjh[(size_t)MM*MM];
__device__ __nv_bfloat16 g_adjl[(size_t)MM*MM];
__device__ __nv_bfloat16 g_Bh[(size_t)BB*DG*MM];
__device__ __nv_bfloat16 g_Bl[(size_t)BB*DG*MM];

__device__ __forceinline__ float sigf(float x){ return 1.f/(1.f+expf(-x)); }
__device__ __forceinline__ float eluf(float x){ return x>0.f ? x : expf(x)-1.f; }
__device__ __forceinline__ float fsig(float x){ return __fdividef(1.f, 1.f + __expf(-x)); }
__device__ __forceinline__ float ftanh(float x){ return 1.f - 2.f*__fdividef(1.f, 1.f + __expf(2.f*x)); }
__device__ __forceinline__ float felu(float x){ return x>0.f ? x : __expf(x)-1.f; }

#define FFMA2(acc, a, b) asm("fma.rn.f32x2 %0, %1, %2, %0;" : "+l"(acc) : "l"(a), "l"(b))
#define ADDF2(o, a, b)   asm("add.rn.f32x2 %0, %1, %2;" : "=l"(o) : "l"(a), "l"(b))
#define PACK2(p, lo, hi) asm("mov.b64 %0, {%1, %2};" : "=l"(p) : "f"(lo), "f"(hi))
#define PACKB(p, v)      asm("mov.b64 %0, {%1, %1};" : "=l"(p) : "f"(v))
#define UNPACK2(lo, hi, p) asm("mov.b64 {%0, %1}, %2;" : "=f"(lo), "=f"(hi) : "l"(p))

#define MMA16816(d, a0,a1,a2,a3, b0,b1) \
    asm volatile("mma.sync.aligned.m16n8k16.row.col.f32.bf16.bf16.f32 " \
        "{%0,%1,%2,%3}, {%4,%5,%6,%7}, {%8,%9}, {%0,%1,%2,%3};" \
        : "+f"((d)[0]), "+f"((d)[1]), "+f"((d)[2]), "+f"((d)[3]) \
        : "r"(a0), "r"(a1), "r"(a2), "r"(a3), "r"(b0), "r"(b1))

#define LDSM_X4(r0,r1,r2,r3, addr) \
    asm volatile("ldmatrix.sync.aligned.m8n8.x4.shared.b16 {%0,%1,%2,%3}, [%4];" \
        : "=r"(r0), "=r"(r1), "=r"(r2), "=r"(r3) : "r"(addr))
#define LDSM_X2(r0,r1, addr) \
    asm volatile("ldmatrix.sync.aligned.m8n8.x2.shared.b16 {%0,%1}, [%2];" \
        : "=r"(r0), "=r"(r1) : "r"(addr))

__device__ __forceinline__ uint32_t smem_u32(const void* p){
    uint32_t a;
    asm("{ .reg .u64 t; cvta.to.shared.u64 t, %1; cvt.u32.u64 %0, t; }" : "=r"(a) : "l"(p));
    return a;
}

// ---------------- 1) h_SC ----------------
__global__ void k_hsc(const float* __restrict__ x, const float* __restrict__ Wt,
                      const float* __restrict__ bt){
    __shared__ float xs[WW*256];
    __shared__ float sWt[WW*HSCD];
    __shared__ float sbt[HSCD];
    int b = blockIdx.x, mt = blockIdx.y, tid = threadIdx.x;
    int m0 = mt*256;
    #pragma unroll
    for (int w = 0; w < WW; ++w) xs[w*256+tid] = x[(b*WW+w)*MM + m0 + tid];
    for (int i = tid; i < WW*HSCD; i += 256) sWt[i] = Wt[i];
    if (tid < HSCD) sbt[tid] = bt[tid];
    __syncthreads();
    float hv[HSCD];
    #pragma unroll
    for (int k = 0; k < HSCD; ++k) hv[k] = sbt[k];
    #pragma unroll
    for (int w = 0; w < WW; ++w){
        float xv = xs[w*256+tid];
        #pragma unroll
        for (int k = 0; k < HSCD; ++k) hv[k] = fmaf(xv, sWt[w*HSCD+k], hv[k]);
    }
    float* op = &g_hSC[(size_t)(b*MM + m0 + tid)*HSCD];
    #pragma unroll
    for (int k = 0; k < HSCD; ++k) op[k] = hv[k];
}

// ---------------- 2) key sum + Gram partials ----------------
__global__ void k_kstats(const float* __restrict__ WKw, const float* __restrict__ WKb){
    __shared__ float sW[HSCD*HID + HID];
    __shared__ float Ks[256*33];
    int b = blockIdx.x, ch = blockIdx.y, tid = threadIdx.x;
    for (int i = tid; i < HSCD*HID + HID; i += 256)
        sW[i] = (i < HSCD*HID) ? WKw[i] : WKb[i - HSCD*HID];
    __syncthreads();
    int m = ch*256 + tid;
    const float* hp = &g_hSC[(size_t)(b*MM+m)*HSCD];
    float hc[HSCD];
    #pragma unroll
    for (int c = 0; c < HSCD; ++c) hc[c] = hp[c];
    #pragma unroll
    for (int h = 0; h < HID; ++h){
        float a = sW[HSCD*HID + h];
        #pragma unroll
        for (int c = 0; c < HSCD; ++c) a = fmaf(hc[c], sW[c*HID+h], a);
        Ks[tid*33 + h] = a;
    }
    __syncthreads();
    float* outp = &g_kpart[(size_t)(b*8 + ch)*1056];
    #pragma unroll
    for (int e = 0; e < 4; ++e){
        int idx = tid*4 + e, i = idx >> 5, j = idx & 31;
        float s = 0.f;
        for (int r = 0; r < 256; ++r) s = fmaf(Ks[r*33+i], Ks[r*33+j], s);
        outp[idx] = s;
    }
    if (tid < 32){
        float s = 0.f;
        for (int r = 0; r < 256; ++r) s += Ks[r*33+tid];
        outp[1024+tid] = s;
    }
}

__global__ void k_kreduce(){
    int b = blockIdx.x, tid = threadIdx.x;
    for (int idx = tid; idx < 1056; idx += 256){
        float s = 0.f;
        #pragma unroll
        for (int c = 0; c < 8; ++c) s += g_kpart[(size_t)(b*8+c)*1056 + idx];
        if (idx < 1024) g_gram[b*1024+idx] = s;
        else            g_ksum[b*32 + idx - 1024] = s;
    }
}

// ---------------- 4+5) GRU fused with score; 4-way split accumulators ----------------
__global__ void __launch_bounds__(256,2) k_gru(const float* __restrict__ x, const float* __restrict__ wih,
                      const float* __restrict__ whh, const float* __restrict__ bih,
                      const float* __restrict__ bhh,
                      const float* __restrict__ W1, const float* __restrict__ W2,
                      const float* __restrict__ b1, const float* __restrict__ V,
                      const float* __restrict__ bv){
    __shared__ float sW12[512];
    __shared__ float sV[16], sb1[16];
    __shared__ __align__(16) float sH[8*32];
    int tid = threadIdx.x, lane = tid & 31, wid = tid >> 5;
    for (int i = tid; i < 512; i += 256) sW12[i] = W1[i] + W2[i];
    if (tid < 16){ sV[tid] = V[tid]; sb1[tid] = b1[tid]; }
    __syncthreads();
    int seq = blockIdx.x*8 + wid;
    int b = seq >> 11, m = seq & 2047;
    const float4* pr = (const float4*)&whh[lane*32];
    const float4* pz = (const float4*)&whh[(lane+32)*32];
    const float4* pn = (const float4*)&whh[(lane+64)*32];
    unsigned long long prz[32];
    float wn[32];
    #pragma unroll
    for (int k = 0; k < 8; ++k){
        float4 r4 = pr[k], z4 = pz[k], n4 = pn[k];
        PACK2(prz[k*4+0], r4.x, z4.x);
        PACK2(prz[k*4+1], r4.y, z4.y);
        PACK2(prz[k*4+2], r4.z, z4.z);
        PACK2(prz[k*4+3], r4.w, z4.w);
        wn[k*4+0] = n4.x; wn[k*4+1] = n4.y; wn[k*4+2] = n4.z; wn[k*4+3] = n4.w;
    }
    float wxr = wih[lane], wxz = wih[32+lane], wxn = wih[64+lane];
    float bxr = bih[lane], bxz = bih[32+lane], bxn = bih[64+lane];
    unsigned long long brz; PACK2(brz, bhh[lane], bhh[32+lane]);
    float bn = bhh[64+lane];
    float xv = (lane < WW) ? x[(b*WW+lane)*MM + m] : 0.f;
    float* myH = &sH[wid*32];
    float h = 0.f;
    for (int t = 0; t < WW; ++t){
        float xt = __shfl_sync(0xffffffffu, xv, t);
        myH[lane] = h;
        __syncwarp();
        unsigned long long arz0 = brz, arz1 = 0ULL, arz2 = 0ULL, arz3 = 0ULL;
        float an0 = bn, an1 = 0.f, an2 = 0.f, an3 = 0.f;
        #pragma unroll
        for (int k = 0; k < 8; ++k){
            float4 h4 = *(const float4*)&myH[k*4];
            unsigned long long p0, p1, p2, p3;
            PACKB(p0, h4.x); PACKB(p1, h4.y); PACKB(p2, h4.z); PACKB(p3, h4.w);
            FFMA2(arz0, prz[k*4+0], p0);
            FFMA2(arz1, prz[k*4+1], p1);
            FFMA2(arz2, prz[k*4+2], p2);
            FFMA2(arz3, prz[k*4+3], p3);
            an0 = fmaf(wn[k*4+0], h4.x, an0);
            an1 = fmaf(wn[k*4+1], h4.y, an1);
            an2 = fmaf(wn[k*4+2], h4.z, an2);
            an3 = fmaf(wn[k*4+3], h4.w, an3);
        }
        __syncwarp();
        unsigned long long s01, s23, sall;
        ADDF2(s01, arz0, arz1);
        ADDF2(s23, arz2, arz3);
        ADDF2(sall, s01, s23);
        float ar, az; UNPACK2(ar, az, sall);
        float an = (an0 + an1) + (an2 + an3);
        float r = fsig(fmaf(xt, wxr, bxr) + ar);
        float z = fsig(fmaf(xt, wxz, bxz) + az);
        float n = ftanh(fmaf(xt, wxn, bxn) + r*an);
        h = (1.f - z)*n + z*h;
    }
    g_hT[(size_t)seq*32 + lane] = h;
    myH[lane] = h;
    __syncwarp();
    float ao = (lane < 16) ? sb1[lane] : 0.f;
    #pragma unroll
    for (int k = 0; k < 8; ++k){
        float4 h4 = *(const float4*)&myH[k*4];
        const float* wrow = &sW12[(lane & 15)*32 + k*4];
        ao = fmaf(h4.x, wrow[0], ao);
        ao = fmaf(h4.y, wrow[1], ao);
        ao = fmaf(h4.z, wrow[2], ao);
        ao = fmaf(h4.w, wrow[3], ao);
    }
    float so = (lane < 16) ? felu(ao)*sV[lane] : 0.f;
    #pragma unroll
    for (int o = 8; o; o >>= 1) so += __shfl_down_sync(0xffffffffu, so, o);
    if (lane == 0){
        float s = so + bv[0];
        g_t[seq] = s / fmaxf(fabsf(s)*45.254833995939045f, 1e-12f);
    }
}

// ---------------- 3+9) rownorm fused with node0 build ----------------
__global__ void k_rownorm(const float* __restrict__ WQw, const float* __restrict__ WQb,
                          const float* __restrict__ tenc_w, const float* __restrict__ tenc_b,
                          const float* __restrict__ senc_w, const float* __restrict__ senc_b,
                          const float* __restrict__ degree){
    __shared__ float sW[HSCD*HID];
    __shared__ float sb[HID];
    __shared__ float sG[1024];
    __shared__ float sk[32];
    __shared__ float senc[4*32];
    int b = blockIdx.x, tid = threadIdx.x;
    for (int i = tid; i < HSCD*HID; i += 256) sW[i] = WQw[i];
    if (tid < HID) sb[tid] = WQb[tid];
    for (int i = tid; i < 1024; i += 256) sG[i] = g_gram[b*1024+i];
    if (tid < 32) sk[tid] = g_ksum[b*32+tid];
    if (tid < 32){
        senc[tid] = senc_w[tid]; senc[32+tid] = senc_b[tid];
        senc[64+tid] = tenc_w[tid]; senc[96+tid] = tenc_b[tid];
    }
    __syncthreads();
    int m = blockIdx.y*256 + tid;
    const float* hp = &g_hSC[(size_t)(b*MM+m)*HSCD];
    float hc[HSCD];
    #pragma unroll
    for (int c = 0; c < HSCD; ++c) hc[c] = hp[c];
    float q[HID];
    #pragma unroll
    for (int h = 0; h < HID; ++h){
        float a = sb[h];
        #pragma unroll
        for (int c = 0; c < HSCD; ++c) a = fmaf(hc[c], sW[c*HID+h], a);
        q[h] = a;
    }
    float num = 0.f, den = 0.f;
    #pragma unroll
    for (int h = 0; h < HID; ++h) num = fmaf(q[h], sk[h], num);
    #pragma unroll
    for (int i = 0; i < HID; ++i){
        float tmp = 0.f;
        #pragma unroll
        for (int j = 0; j < HID; ++j) tmp = fmaf(sG[i*32+j], q[j], tmp);
        den = fmaf(q[i], tmp, den);
    }
    float rn = num / fmaxf(sqrtf(fmaxf(den, 0.f)), 1e-12f);
    float* np = &g_node0[(size_t)(b*MM+m)*DG];
    #pragma unroll
    for (int c = 0; c < HSCD; ++c) np[c] = hc[c];
    float dm = degree[m];
    #pragma unroll
    for (int h = 0; h < 32; ++h) np[16+h] = fmaf(dm, senc[h], senc[32+h]);
    #pragma unroll
    for (int h = 0; h < 32; ++h) np[48+h] = fmaf(rn, senc[64+h], senc[96+h]);
}

// ---------------- 6) c_gate ----------------
__global__ void k_cg_part(const float* __restrict__ Wb){
    __shared__ float ts[8*128];
    int jt = blockIdx.x, nc = blockIdx.y, tid = threadIdx.x;
    int n0 = nc*128;
    for (int idx = tid; idx < 1024; idx += 256){
        int bb = idx >> 7, nn = idx & 127;
        ts[idx] = g_t[bb*MM + n0 + nn];
    }
    __syncthreads();
    int j = jt*256 + tid;
    float acc[8] = {0,0,0,0,0,0,0,0};
    for (int nn = 0; nn < 128; ++nn){
        float w = Wb[(size_t)(n0+nn)*MM + j];
        #pragma unroll
        for (int bb = 0; bb < 8; ++bb) acc[bb] = fmaf(ts[bb*128+nn], w, acc[bb]);
    }
    #pragma unroll
    for (int bb = 0; bb < 8; ++bb) g_cgp[(size_t)(nc*8+bb)*MM + j] = acc[bb];
}

__global__ void k_cg_fin(const float* __restrict__ wb){
    int gid = blockIdx.x*256 + threadIdx.x;
    int b = gid >> 11, j = gid & 2047;
    float s = wb[0];
    #pragma unroll
    for (int nc = 0; nc < 16; ++nc) s += g_cgp[(size_t)(nc*8+b)*MM + j];
    float c = sigf(s);
    g_c[gid] = c;
    g_tc[gid] = g_t[gid]*(1.f - c);
}

// ---------------- 7) sparse spatial ----------------
__global__ void k_spatial(const float* __restrict__ d_gate, const float* __restrict__ adj_orig,
                          const float* __restrict__ degree){
    int tid = threadIdx.x, lane = tid & 31, wid = tid >> 5;
    int i = blockIdx.x*8 + wid;
    float di = degree[i];
    int cnt = 0;
    for (int j0 = 0; j0 < MM; j0 += 32){
        int j = j0 + lane;
        float a = adj_orig[(size_t)i*MM + j];
        bool nz = a > 0.f;
        unsigned mask = __ballot_sync(0xffffffffu, nz);
        if (nz){
            float v = a * sigf(d_gate[(size_t)i*MM + j]*di*degree[j]);
            int pos = cnt + __popc(mask & ((1u << lane) - 1u));
            if (pos < SPCAP){ g_spi[i*SPCAP+pos] = j; g_spv[i*SPCAP+pos] = v; }
        }
        cnt += __popc(mask);
    }
    if (lane == 0) g_spc[i] = min(cnt, SPCAP);
}

// ---------------- 8) degree counts ----------------
__global__ void k_deg(const float* __restrict__ adj_geo){
    __shared__ float cs[8*512];
    __shared__ float tcs[8*512];
    int tid = threadIdx.x, lane = tid & 31, w = tid >> 5;
    int i = blockIdx.x*8 + w;
    int cnt[8] = {0,0,0,0,0,0,0,0};
    for (int j0 = 0; j0 < MM; j0 += 512){
        __syncthreads();
        for (int idx = tid; idx < 4096; idx += 256){
            int bb = idx >> 9, jj = idx & 511;
            cs[idx]  = g_c[bb*MM + j0 + jj];
            tcs[idx] = g_tc[bb*MM + j0 + jj];
        }
        __syncthreads();
        for (int j = lane; j < 512; j += 32){
            float ag = adj_geo[(size_t)i*MM + j0 + j];
            #pragma unroll
            for (int bb = 0; bb < 8; ++bb){
                float dyn = fmaf(ag, cs[bb*512+j], tcs[bb*512+j]);
                cnt[bb] += (dyn > 0.f);
            }
        }
    }
    int sc = g_spc[i];
    for (int s = lane; s < sc; s += 32){
        int j = g_spi[i*SPCAP+s]; float v = g_spv[i*SPCAP+s];
        float ag = adj_geo[(size_t)i*MM + j];
        #pragma unroll
        for (int bb = 0; bb < 8; ++bb){
            float dyn = fmaf(ag, g_c[bb*MM+j], g_tc[bb*MM+j]);
            if (dyn <= 0.f && dyn + v > 0.f) cnt[bb]++;
        }
    }
    #pragma unroll
    for (int bb = 0; bb < 8; ++bb){
        int vv = cnt[bb];
        #pragma unroll
        for (int o = 16; o; o >>= 1) vv += __shfl_down_sync(0xffffffffu, vv, o);
        if (lane == 0) g_dinv[bb*MM + i] = (vv > 0) ? 1.f/(float)vv : 0.f;
    }
}

// ---------------- adj -> bf16 hi/lo (once) ----------------
__global__ void k_adjcvt(const float* __restrict__ adj){
    size_t idx = (size_t)blockIdx.x*256 + threadIdx.x;   // over 2M float2
    float2 v = ((const float2*)adj)[idx];
    __nv_bfloat162 h2 = __floats2bfloat162_rn(v.x, v.y);
    float hx = __bfloat162float(__low2bfloat16(h2));
    float hy = __bfloat162float(__high2bfloat16(h2));
    __nv_bfloat162 l2 = __floats2bfloat162_rn(v.x - hx, v.y - hy);
    *(__nv_bfloat162*)&g_adjh[idx*2] = h2;
    *(__nv_bfloat162*)&g_adjl[idx*2] = l2;
}

// ---------------- B matrix build + u partials ----------------
__global__ void k_bmat(const float* __restrict__ node){
    __shared__ float sT[64*DG];
    __shared__ float su[DG];
    int j0 = blockIdx.x*64, b = blockIdx.y, tid = threadIdx.x;
    if (tid < DG) su[tid] = 0.f;
    __syncthreads();
    for (int idx = tid; idx < 64*DG; idx += 256){
        int j = idx/DG, d = idx%DG;
        float nv = node[(size_t)(b*MM + j0 + j)*DG + d];
        sT[idx] = g_c[b*MM + j0 + j] * nv;
        atomicAdd(&su[d], g_tc[b*MM + j0 + j] * nv);
    }
    __syncthreads();
    for (int idx = tid; idx < 64*DG; idx += 256){
        int d = idx >> 6, jj = idx & 63;
        float v = sT[jj*DG + d];
        __nv_bfloat16 h = __float2bfloat16(v);
        __nv_bfloat16 l = __float2bfloat16(v - __bfloat162float(h));
        size_t o = (size_t)(b*DG + d)*MM + j0 + jj;
        g_Bh[o] = h; g_Bl[o] = l;
    }
    if (tid < DG) g_upart[(b*32 + blockIdx.x)*DG + tid] = su[tid];
}

// ---------------- 11) fused GNN layer: mma.sync bf16 split, 512 threads ----------------
__global__ void __launch_bounds__(512,1) k_gemm(const float* __restrict__ nodeIn, float* __restrict__ nodeOut,
                       const float* __restrict__ gw, const float* __restrict__ gb){
    extern __shared__ char dsm[];
    __shared__ __align__(16) float sU[DG];
    __nv_bfloat16* sAh = (__nv_bfloat16*)dsm;
    __nv_bfloat16* sAl = (__nv_bfloat16*)(dsm + 18432);
    __nv_bfloat16* sBh = (__nv_bfloat16*)(dsm + 36864);
    __nv_bfloat16* sBl = (__nv_bfloat16*)(dsm + 48384);
    float* sY = (float*)dsm;
    float* sG = (float*)(dsm + 43008);

    int tid = threadIdx.x, lane = tid & 31, wid = tid >> 5;
    int i0 = blockIdx.x*128, b = blockIdx.y;
    int mBase = (wid >> 1)*16, nBase = (wid & 1)*40;
    int gid = lane >> 2, t2 = (lane & 3)*2;

    uint32_t aBase = smem_u32(sAh) + (uint32_t)((mBase + (lane & 15))*144 + (lane >> 4)*16);
    uint32_t bBase = smem_u32(sBh) + (uint32_t)((nBase + (lane & 7))*144 + ((lane >> 3) & 1)*16);

    // reduce u partials into sU
    if (tid < DG){
        float s = 0.f;
        #pragma unroll 8
        for (int p = 0; p < 32; ++p) s += g_upart[(b*32 + p)*DG + tid];
        sU[tid] = s;
    }

    int ra[2], sa[2];
    #pragma unroll
    for (int e = 0; e < 2; ++e){ int p = tid + e*512; ra[e] = p >> 3; sa[e] = (p & 7)*8; }
    int p1 = tid;
    int db0 = p1 >> 3, sb0 = (p1 & 7)*8;
    int p2 = tid + 512;
    int db1 = p2 >> 3, sb1v = (p2 & 7)*8;
    bool hasB1 = (p2 < 640);

    uint4 pAh[2], pAl[2], pBh0, pBl0, pBh1, pBl1;
    #pragma unroll
    for (int e = 0; e < 2; ++e){
        size_t o = (size_t)(i0 + ra[e])*MM + sa[e];
        pAh[e] = *(const uint4*)&g_adjh[o];
        pAl[e] = *(const uint4*)&g_adjl[o];
    }
    {
        size_t o = (size_t)(b*DG + db0)*MM + sb0;
        pBh0 = *(const uint4*)&g_Bh[o];
        pBl0 = *(const uint4*)&g_Bl[o];
        if (hasB1){
            size_t o1 = (size_t)(b*DG + db1)*MM + sb1v;
            pBh1 = *(const uint4*)&g_Bh[o1];
            pBl1 = *(const uint4*)&g_Bl[o1];
        }
    }

    float acc[5][4];
    #pragma unroll
    for (int n = 0; n < 5; ++n)
        #pragma unroll
        for (int k = 0; k < 4; ++k) acc[n][k] = 0.f;

    for (int jt = 0; jt < 32; ++jt){
        __syncthreads();
        #pragma unroll
        for (int e = 0; e < 2; ++e){
            *(uint4*)&sAh[ra[e]*72 + sa[e]] = pAh[e];
            *(uint4*)&sAl[ra[e]*72 + sa[e]] = pAl[e];
        }
        *(uint4*)&sBh[db0*72 + sb0] = pBh0;
        *(uint4*)&sBl[db0*72 + sb0] = pBl0;
        if (hasB1){
            *(uint4*)&sBh[db1*72 + sb1v] = pBh1;
            *(uint4*)&sBl[db1*72 + sb1v] = pBl1;
        }
        if (jt + 1 < 32){
            int j0 = (jt+1)*64;
            #pragma unroll
            for (int e = 0; e < 2; ++e){
                size_t o = (size_t)(i0 + ra[e])*MM + j0 + sa[e];
                pAh[e] = *(const uint4*)&g_adjh[o];
                pAl[e] = *(const uint4*)&g_adjl[o];
            }
            size_t o = (size_t)(b*DG + db0)*MM + j0 + sb0;
            pBh0 = *(const uint4*)&g_Bh[o];
            pBl0 = *(const uint4*)&g_Bl[o];
            if (hasB1){
                size_t o1 = (size_t)(b*DG + db1)*MM + j0 + sb1v;
                pBh1 = *(const uint4*)&g_Bh[o1];
                pBl1 = *(const uint4*)&g_Bl[o1];
            }
        }
        __syncthreads();
        #pragma unroll
        for (int ks = 0; ks < 4; ++ks){
            uint32_t aA = aBase + ks*32;
            uint32_t ah0, ah1, ah2, ah3, al0, al1, al2, al3;
            LDSM_X4(ah0, ah1, ah2, ah3, aA);
            LDSM_X4(al0, al1, al2, al3, aA + 18432);
            #pragma unroll
            for (int nt = 0; nt < 5; ++nt){
                uint32_t bA = bBase + nt*1152 + ks*32;
                uint32_t bh0, bh1, bl0, bl1;
                LDSM_X2(bh0, bh1, bA);
                LDSM_X2(bl0, bl1, bA + 11520);
                MMA16816(acc[nt], ah0, ah1, ah2, ah3, bh0, bh1);
                MMA16816(acc[nt], ah0, ah1, ah2, ah3, bl0, bl1);
                MMA16816(acc[nt], al0, al1, al2, al3, bh0, bh1);
            }
        }
    }
    __syncthreads();
    #pragma unroll
    for (int nt = 0; nt < 5; ++nt){
        int col = nBase + nt*8 + t2;
        sY[(mBase+gid)*84   + col]     = acc[nt][0];
        sY[(mBase+gid)*84   + col + 1] = acc[nt][1];
        sY[(mBase+gid+8)*84 + col]     = acc[nt][2];
        sY[(mBase+gid+8)*84 + col + 1] = acc[nt][3];
    }
    for (int idx = tid; idx < 6400; idx += 512)
        sG[(idx/80)*84 + idx%80] = gw[idx];
    __syncthreads();

    int q = tid & 3, ig = tid >> 2;   // ig in [0,128)
    // ---- pass 1: sparse + rank-1 + deg scaling ----
    {
        int row = ig;
        int i = i0 + row;
        float a20[20];
        float4* yp = (float4*)&sY[row*84 + q*20];
        #pragma unroll
        for (int v = 0; v < 5; ++v){
            float4 y4 = yp[v];
            a20[v*4+0] = y4.x; a20[v*4+1] = y4.y; a20[v*4+2] = y4.z; a20[v*4+3] = y4.w;
        }
        int sc = g_spc[i];
        for (int s = 0; s < sc; ++s){
            int j = g_spi[i*SPCAP+s]; float v = g_spv[i*SPCAP+s];
            const float4* np = (const float4*)&nodeIn[(size_t)(b*MM + j)*DG + q*20];
            #pragma unroll
            for (int vv = 0; vv < 5; ++vv){
                float4 n = np[vv];
                a20[vv*4+0] = fmaf(v, n.x, a20[vv*4+0]);
                a20[vv*4+1] = fmaf(v, n.y, a20[vv*4+1]);
                a20[vv*4+2] = fmaf(v, n.z, a20[vv*4+2]);
                a20[vv*4+3] = fmaf(v, n.w, a20[vv*4+3]);
            }
        }
        float dinv = g_dinv[b*MM + i];
        const float4* up = (const float4*)&sU[q*20];
        #pragma unroll
        for (int vv = 0; vv < 5; ++vv){
            float4 u4 = up[vv];
            float4 y;
            y.x = dinv*(a20[vv*4+0] + u4.x);
            y.y = dinv*(a20[vv*4+1] + u4.y);
            y.z = dinv*(a20[vv*4+2] + u4.z);
            y.w = dinv*(a20[vv*4+3] + u4.w);
            yp[vv] = y;
        }
    }
    __syncthreads();
    // ---- pass 2: z = y @ gw + gb, elu ----
    {
        int i = i0 + ig;
        unsigned long long z2[10];
        const float2* gb2 = (const float2*)&gb[q*20];
        #pragma unroll
        for (int k = 0; k < 10; ++k){ float2 g2 = gb2[k]; PACK2(z2[k], g2.x, g2.y); }
        for (int d = 0; d < 80; ++d){
            float yv = sY[ig*84 + d];
            unsigned long long py; PACKB(py, yv);
            const ulonglong2* gp = (const ulonglong2*)&sG[d*84 + q*20];
            #pragma unroll
            for (int v = 0; v < 5; ++v){
                ulonglong2 g2 = gp[v];
                FFMA2(z2[v*2],   py, g2.x);
                FFMA2(z2[v*2+1], py, g2.y);
            }
        }
        float* op = &nodeOut[(size_t)(b*MM + i)*DG + q*20];
        #pragma unroll
        for (int v = 0; v < 5; ++v){
            float4 o4;
            float za, zbv, zc, zd;
            UNPACK2(za, zbv, z2[v*2]);
            UNPACK2(zc, zd, z2[v*2+1]);
            o4.x = eluf(za); o4.y = eluf(zbv); o4.z = eluf(zc); o4.w = eluf(zd);
            *(float4*)&op[v*4] = o4;
        }
    }
}

// ---------------- 12) final projection (float4 rows) ----------------
__global__ void k_final(const float* __restrict__ out_w, const float* __restrict__ out_b,
                        float* __restrict__ out){
    __shared__ float sw[272];
    int tid = threadIdx.x;
    for (int i = tid; i < 272; i += 256) sw[i] = out_w[i];
    __syncthreads();
    int gid = blockIdx.x*256 + tid;
    float a = out_b[0];
    const float4* n0 = (const float4*)&g_node0[(size_t)gid*DG];
    const float4* n1 = (const float4*)&g_node1[(size_t)gid*DG];
    const float4* n2 = (const float4*)&g_node2[(size_t)gid*DG];
    const float4* ht = (const float4*)&g_hT[(size_t)gid*32];
    #pragma unroll
    for (int k = 0; k < 20; ++k){
        float4 v = n0[k];
        const float* w = &sw[k*4];
        a = fmaf(v.x, w[0], a); a = fmaf(v.y, w[1], a);
        a = fmaf(v.z, w[2], a); a = fmaf(v.w, w[3], a);
    }
    #pragma unroll
    for (int k = 0; k < 20; ++k){
        float4 v = n1[k];
        const float* w = &sw[80 + k*4];
        a = fmaf(v.x, w[0], a); a = fmaf(v.y, w[1], a);
        a = fmaf(v.z, w[2], a); a = fmaf(v.w, w[3], a);
    }
    #pragma unroll
    for (int k = 0; k < 20; ++k){
        float4 v = n2[k];
        const float* w = &sw[160 + k*4];
        a = fmaf(v.x, w[0], a); a = fmaf(v.y, w[1], a);
        a = fmaf(v.z, w[2], a); a = fmaf(v.w, w[3], a);
    }
    #pragma unroll
    for (int k = 0; k < 8; ++k){
        float4 v = ht[k];
        const float* w = &sw[240 + k*4];
        a = fmaf(v.x, w[0], a); a = fmaf(v.y, w[1], a);
        a = fmaf(v.z, w[2], a); a = fmaf(v.w, w[3], a);
    }
    out[gid] = a;
}

// ---------------- launch ----------------
extern "C" void kernel_launch(void* const* d_in, const int* in_sizes, int n_in,
                              void* d_out, int out_size){
    const float* x       = (const float*)d_in[0];
    const float* Wt      = (const float*)d_in[1];
    const float* bt      = (const float*)d_in[2];
    const float* WQ_w    = (const float*)d_in[3];
    const float* WQ_b    = (const float*)d_in[4];
    const float* WK_w    = (const float*)d_in[5];
    const float* WK_b    = (const float*)d_in[6];
    const float* tenc_w  = (const float*)d_in[7];
    const float* tenc_b  = (const float*)d_in[8];
    const float* senc_w  = (const float*)d_in[9];
    const float* senc_b  = (const float*)d_in[10];
    const float* gru_wih = (const float*)d_in[11];
    const float* gru_whh = (const float*)d_in[12];
    const float* gru_bih = (const float*)d_in[13];
    const float* gru_bhh = (const float*)d_in[14];
    const float* V       = (const float*)d_in[15];
    const float* bv      = (const float*)d_in[16];
    const float* W1      = (const float*)d_in[17];
    const float* b1      = (const float*)d_in[18];
    const float* W2      = (const float*)d_in[19];
    const float* Wb      = (const float*)d_in[20];
    const float* wb      = (const float*)d_in[21];
    const float* d_gate  = (const float*)d_in[22];
    const float* adj_geo = (const float*)d_in[23];
    const float* adj_orig= (const float*)d_in[24];
    const float* degree  = (const float*)d_in[25];
    const float* gnn_w   = (const float*)d_in[26];
    const float* gnn_b   = (const float*)d_in[27];
    const float* out_w   = (const float*)d_in[28];
    const float* out_b   = (const float*)d_in[29];
    float* out = (float*)d_out;

    const int GEMM_SMEM = 69888;
    cudaFuncSetAttribute(k_gemm, cudaFuncAttributeMaxDynamicSharedMemorySize, GEMM_SMEM);

    float *n0, *n1, *n2;
    cudaGetSymbolAddress((void**)&n0, g_node0);
    cudaGetSymbolAddress((void**)&n1, g_node1);
    cudaGetSymbolAddress((void**)&n2, g_node2);

    k_adjcvt<<<MM*MM/2/256, 256>>>(adj_geo);
    k_hsc<<<dim3(BB, MM/256), 256>>>(x, Wt, bt);
    k_kstats<<<dim3(BB, 8), 256>>>(WK_w, WK_b);
    k_kreduce<<<BB, 256>>>();
    k_gru<<<BB*MM/8, 256>>>(x, gru_wih, gru_whh, gru_bih, gru_bhh,
                            W1, W2, b1, V, bv);
    k_rownorm<<<dim3(BB, MM/256), 256>>>(WQ_w, WQ_b, tenc_w, tenc_b,
                                         senc_w, senc_b, degree);
    k_cg_part<<<dim3(8, 16), 256>>>(Wb);
    k_cg_fin<<<BB*MM/256, 256>>>(wb);
    k_spatial<<<MM/8, 256>>>(d_gate, adj_orig, degree);
    k_deg<<<MM/8, 256>>>(adj_geo);
    k_bmat<<<dim3(MM/64, BB), 256>>>(n0);
    k_gemm<<<dim3(MM/128, BB), 512, GEMM_SMEM>>>(n0, n1, gnn_w, gnn_b);
    k_bmat<<<dim3(MM/64, BB), 256>>>(n1);
    k_gemm<<<dim3(MM/128, BB), 512, GEMM_SMEM>>>(n1, n2, gnn_w + 6400, gnn_b + 80);
    k_final<<<BB*MM/256, 256>>>(out_w, out_b, out);
}

// round 16
// speedup vs baseline: 1.2057x; 1.1918x over previous
#include <cuda_runtime.h>
#include <cuda_bf16.h>
#include <math.h>
#include <stdint.h>

#define BB 8
#define WW 20
#define MM 2048
#define HSCD 16
#define HID 32
#define NHH 32
#define DG 80
#define SPCAP 96

// ---------------- scratch (device globals; no allocations) ----------------
__device__ float g_hSC[BB*MM*HSCD];
__device__ float g_kpart[BB*8*1056];
__device__ float g_gram[BB*1024];
__device__ float g_ksum[BB*32];
__device__ float g_hT[BB*MM*NHH];
__device__ float g_t[BB*MM];
__device__ float g_cgp[16*BB*MM];
__device__ float g_c[BB*MM];
__device__ float g_tc[BB*MM];
__device__ float g_spv[MM*SPCAP];
__device__ int   g_spi[MM*SPCAP];
__device__ int   g_spc[MM];
__device__ float g_dinv[BB*MM];
__device__ float g_node0[BB*MM*DG];
__device__ float g_node1[BB*MM*DG];
__device__ float g_node2[BB*MM*DG];
__device__ float g_upart[BB*32*DG];
// bf16 split operands
__device__ __nv_bfloat16 g_adjh[(size_t)MM*MM];
__device__ __nv_bfloat16 g_adjl[(size_t)MM*MM];
__device__ __nv_bfloat16 g_Bh[(size_t)BB*DG*MM];
__device__ __nv_bfloat16 g_Bl[(size_t)BB*DG*MM];

__device__ __forceinline__ float sigf(float x){ return 1.f/(1.f+expf(-x)); }
__device__ __forceinline__ float eluf(float x){ return x>0.f ? x : expf(x)-1.f; }
__device__ __forceinline__ float fsig(float x){ return __fdividef(1.f, 1.f + __expf(-x)); }
__device__ __forceinline__ float ftanh(float x){ return 1.f - 2.f*__fdividef(1.f, 1.f + __expf(2.f*x)); }
__device__ __forceinline__ float felu(float x){ return x>0.f ? x : __expf(x)-1.f; }

#define FFMA2(acc, a, b) asm("fma.rn.f32x2 %0, %1, %2, %0;" : "+l"(acc) : "l"(a), "l"(b))
#define PACK2(p, lo, hi) asm("mov.b64 %0, {%1, %2};" : "=l"(p) : "f"(lo), "f"(hi))
#define PACKB(p, v)      asm("mov.b64 %0, {%1, %1};" : "=l"(p) : "f"(v))
#define UNPACK2(lo, hi, p) asm("mov.b64 {%0, %1}, %2;" : "=f"(lo), "=f"(hi) : "l"(p))

#define MMA16816(d, a0,a1,a2,a3, b0,b1) \
    asm volatile("mma.sync.aligned.m16n8k16.row.col.f32.bf16.bf16.f32 " \
        "{%0,%1,%2,%3}, {%4,%5,%6,%7}, {%8,%9}, {%0,%1,%2,%3};" \
        : "+f"((d)[0]), "+f"((d)[1]), "+f"((d)[2]), "+f"((d)[3]) \
        : "r"(a0), "r"(a1), "r"(a2), "r"(a3), "r"(b0), "r"(b1))

#define LDSM_X4(r0,r1,r2,r3, addr) \
    asm volatile("ldmatrix.sync.aligned.m8n8.x4.shared.b16 {%0,%1,%2,%3}, [%4];" \
        : "=r"(r0), "=r"(r1), "=r"(r2), "=r"(r3) : "r"(addr))
#define LDSM_X2(r0,r1, addr) \
    asm volatile("ldmatrix.sync.aligned.m8n8.x2.shared.b16 {%0,%1}, [%2];" \
        : "=r"(r0), "=r"(r1) : "r"(addr))

__device__ __forceinline__ uint32_t smem_u32(const void* p){
    uint32_t a;
    asm("{ .reg .u64 t; cvta.to.shared.u64 t, %1; cvt.u32.u64 %0, t; }" : "=r"(a) : "l"(p));
    return a;
}

// ---------------- 1) h_SC ----------------
__global__ void k_hsc(const float* __restrict__ x, const float* __restrict__ Wt,
                      const float* __restrict__ bt){
    __shared__ float xs[WW*256];
    __shared__ float sWt[WW*HSCD];
    __shared__ float sbt[HSCD];
    int b = blockIdx.x, mt = blockIdx.y, tid = threadIdx.x;
    int m0 = mt*256;
    #pragma unroll
    for (int w = 0; w < WW; ++w) xs[w*256+tid] = x[(b*WW+w)*MM + m0 + tid];
    for (int i = tid; i < WW*HSCD; i += 256) sWt[i] = Wt[i];
    if (tid < HSCD) sbt[tid] = bt[tid];
    __syncthreads();
    float hv[HSCD];
    #pragma unroll
    for (int k = 0; k < HSCD; ++k) hv[k] = sbt[k];
    #pragma unroll
    for (int w = 0; w < WW; ++w){
        float xv = xs[w*256+tid];
        #pragma unroll
        for (int k = 0; k < HSCD; ++k) hv[k] = fmaf(xv, sWt[w*HSCD+k], hv[k]);
    }
    float* op = &g_hSC[(size_t)(b*MM + m0 + tid)*HSCD];
    #pragma unroll
    for (int k = 0; k < HSCD; ++k) op[k] = hv[k];
}

// ---------------- 2) key sum + Gram partials ----------------
__global__ void k_kstats(const float* __restrict__ WKw, const float* __restrict__ WKb){
    __shared__ float sW[HSCD*HID + HID];
    __shared__ float Ks[256*33];
    int b = blockIdx.x, ch = blockIdx.y, tid = threadIdx.x;
    for (int i = tid; i < HSCD*HID + HID; i += 256)
        sW[i] = (i < HSCD*HID) ? WKw[i] : WKb[i - HSCD*HID];
    __syncthreads();
    int m = ch*256 + tid;
    const float* hp = &g_hSC[(size_t)(b*MM+m)*HSCD];
    float hc[HSCD];
    #pragma unroll
    for (int c = 0; c < HSCD; ++c) hc[c] = hp[c];
    #pragma unroll
    for (int h = 0; h < HID; ++h){
        float a = sW[HSCD*HID + h];
        #pragma unroll
        for (int c = 0; c < HSCD; ++c) a = fmaf(hc[c], sW[c*HID+h], a);
        Ks[tid*33 + h] = a;
    }
    __syncthreads();
    float* outp = &g_kpart[(size_t)(b*8 + ch)*1056];
    #pragma unroll
    for (int e = 0; e < 4; ++e){
        int idx = tid*4 + e, i = idx >> 5, j = idx & 31;
        float s = 0.f;
        for (int r = 0; r < 256; ++r) s = fmaf(Ks[r*33+i], Ks[r*33+j], s);
        outp[idx] = s;
    }
    if (tid < 32){
        float s = 0.f;
        for (int r = 0; r < 256; ++r) s += Ks[r*33+tid];
        outp[1024+tid] = s;
    }
}

__global__ void k_kreduce(){
    int b = blockIdx.x, tid = threadIdx.x;
    for (int idx = tid; idx < 1056; idx += 256){
        float s = 0.f;
        #pragma unroll
        for (int c = 0; c < 8; ++c) s += g_kpart[(size_t)(b*8+c)*1056 + idx];
        if (idx < 1024) g_gram[b*1024+idx] = s;
        else            g_ksum[b*32 + idx - 1024] = s;
    }
}

// ---------------- 4+5) GRU via mma.sync bf16-split; 16 seqs/block, fused score ----------------
__global__ void __launch_bounds__(128) k_gru(const float* __restrict__ x, const float* __restrict__ wih,
                      const float* __restrict__ whh, const float* __restrict__ bih,
                      const float* __restrict__ bhh,
                      const float* __restrict__ W1, const float* __restrict__ W2,
                      const float* __restrict__ b1, const float* __restrict__ V,
                      const float* __restrict__ bv){
    __shared__ __align__(16) __nv_bfloat16 sWh[96*40];
    __shared__ __align__(16) __nv_bfloat16 sWl[96*40];
    __shared__ __align__(16) __nv_bfloat16 sHh[2*16*40];
    __shared__ __align__(16) __nv_bfloat16 sHl[2*16*40];
    __shared__ float sX[20*16];
    __shared__ float sHf[16*33];
    __shared__ float sW12[512];
    __shared__ float sV16[16], sb116[16];

    int tid = threadIdx.x, lane = tid & 31, w = tid >> 5;
    int gid = lane >> 2, t2 = (lane & 3)*2;
    int seqBase = blockIdx.x*16;
    int b = seqBase >> 11, mbase = seqBase & 2047;

    // stage whh -> bf16 hi/lo [96][40]
    for (int i = tid; i < 96*32; i += 128){
        int r = i >> 5, c = i & 31;
        float v = whh[i];
        __nv_bfloat16 h = __float2bfloat16(v);
        sWh[r*40 + c] = h;
        sWl[r*40 + c] = __float2bfloat16(v - __bfloat162float(h));
    }
    for (int i = tid; i < 320; i += 128){
        int t = i >> 4, s = i & 15;
        sX[i] = x[(size_t)(b*WW + t)*MM + mbase + s];
    }
    for (int i = tid; i < 2*640; i += 128){
        sHh[i] = __float2bfloat16(0.f);
        sHl[i] = __float2bfloat16(0.f);
    }
    for (int i = tid; i < 512; i += 128) sW12[i] = W1[i] + W2[i];
    if (tid < 16){ sV16[tid] = V[tid]; sb116[tid] = b1[tid]; }
    __syncthreads();

    // B fragments (constant across steps): gate g, k-tile kt, hi/lo
    uint32_t bhf[3][2][2], blf[3][2][2];
    {
        uint32_t rowSel = (uint32_t)(8*w + (lane & 7));
        uint32_t off16 = (uint32_t)(((lane >> 3) & 1)*16);
        uint32_t baseH = smem_u32(sWh), baseL = smem_u32(sWl);
        #pragma unroll
        for (int g = 0; g < 3; ++g)
            #pragma unroll
            for (int kt = 0; kt < 2; ++kt){
                uint32_t aH = baseH + (g*32 + rowSel)*80 + off16 + kt*32;
                LDSM_X2(bhf[g][kt][0], bhf[g][kt][1], aH);
                uint32_t aL = baseL + (g*32 + rowSel)*80 + off16 + kt*32;
                LDSM_X2(blf[g][kt][0], blf[g][kt][1], aL);
            }
    }
    int u0 = 8*w + t2;
    float wxr0 = wih[u0],    wxr1 = wih[u0+1];
    float wxz0 = wih[32+u0], wxz1 = wih[33+u0];
    float wxn0 = wih[64+u0], wxn1 = wih[65+u0];
    float bxr0 = bih[u0],    bxr1 = bih[u0+1];
    float bxz0 = bih[32+u0], bxz1 = bih[33+u0];
    float bxn0 = bih[64+u0], bxn1 = bih[65+u0];
    float bhr0 = bhh[u0],    bhr1 = bhh[u0+1];
    float bhz0 = bhh[32+u0], bhz1 = bhh[33+u0];
    float bhn0 = bhh[64+u0], bhn1 = bhh[65+u0];

    float h00 = 0.f, h01 = 0.f, h10 = 0.f, h11 = 0.f;
    uint32_t aHbase = smem_u32(sHh) + (lane & 15)*80 + (lane >> 4)*16;
    uint32_t aLbase = smem_u32(sHl) + (lane & 15)*80 + (lane >> 4)*16;
    uint32_t sHhW = smem_u32(sHh), sHlW = smem_u32(sHl);

    for (int t = 0; t < WW; ++t){
        int cur = t & 1, nxt = cur ^ 1;
        uint32_t aH = aHbase + cur*1280;
        uint32_t aL = aLbase + cur*1280;
        uint32_t ah0[4], ah1[4], al0[4], al1[4];
        LDSM_X4(ah0[0],ah0[1],ah0[2],ah0[3], aH);
        LDSM_X4(ah1[0],ah1[1],ah1[2],ah1[3], aH + 32);
        LDSM_X4(al0[0],al0[1],al0[2],al0[3], aL);
        LDSM_X4(al1[0],al1[1],al1[2],al1[3], aL + 32);
        float aR[4] = {0,0,0,0}, aZ[4] = {0,0,0,0}, aN[4] = {0,0,0,0};
        // gate r
        MMA16816(aR, ah0[0],ah0[1],ah0[2],ah0[3], bhf[0][0][0], bhf[0][0][1]);
        MMA16816(aR, ah0[0],ah0[1],ah0[2],ah0[3], blf[0][0][0], blf[0][0][1]);
        MMA16816(aR, al0[0],al0[1],al0[2],al0[3], bhf[0][0][0], bhf[0][0][1]);
        MMA16816(aR, ah1[0],ah1[1],ah1[2],ah1[3], bhf[0][1][0], bhf[0][1][1]);
        MMA16816(aR, ah1[0],ah1[1],ah1[2],ah1[3], blf[0][1][0], blf[0][1][1]);
        MMA16816(aR, al1[0],al1[1],al1[2],al1[3], bhf[0][1][0], bhf[0][1][1]);
        // gate z
        MMA16816(aZ, ah0[0],ah0[1],ah0[2],ah0[3], bhf[1][0][0], bhf[1][0][1]);
        MMA16816(aZ, ah0[0],ah0[1],ah0[2],ah0[3], blf[1][0][0], blf[1][0][1]);
        MMA16816(aZ, al0[0],al0[1],al0[2],al0[3], bhf[1][0][0], bhf[1][0][1]);
        MMA16816(aZ, ah1[0],ah1[1],ah1[2],ah1[3], bhf[1][1][0], bhf[1][1][1]);
        MMA16816(aZ, ah1[0],ah1[1],ah1[2],ah1[3], blf[1][1][0], blf[1][1][1]);
        MMA16816(aZ, al1[0],al1[1],al1[2],al1[3], bhf[1][1][0], bhf[1][1][1]);
        // gate n
        MMA16816(aN, ah0[0],ah0[1],ah0[2],ah0[3], bhf[2][0][0], bhf[2][0][1]);
        MMA16816(aN, ah0[0],ah0[1],ah0[2],ah0[3], blf[2][0][0], blf[2][0][1]);
        MMA16816(aN, al0[0],al0[1],al0[2],al0[3], bhf[2][0][0], bhf[2][0][1]);
        MMA16816(aN, ah1[0],ah1[1],ah1[2],ah1[3], bhf[2][1][0], bhf[2][1][1]);
        MMA16816(aN, ah1[0],ah1[1],ah1[2],ah1[3], blf[2][1][0], blf[2][1][1]);
        MMA16816(aN, al1[0],al1[1],al1[2],al1[3], bhf[2][1][0], bhf[2][1][1]);

        float xt0 = sX[t*16 + gid], xt1 = sX[t*16 + gid + 8];
        float r, z, n;
        r = fsig(fmaf(xt0, wxr0, bxr0) + aR[0] + bhr0);
        z = fsig(fmaf(xt0, wxz0, bxz0) + aZ[0] + bhz0);
        n = ftanh(fmaf(xt0, wxn0, bxn0) + r*(aN[0] + bhn0));
        h00 = (1.f - z)*n + z*h00;
        r = fsig(fmaf(xt0, wxr1, bxr1) + aR[1] + bhr1);
        z = fsig(fmaf(xt0, wxz1, bxz1) + aZ[1] + bhz1);
        n = ftanh(fmaf(xt0, wxn1, bxn1) + r*(aN[1] + bhn1));
        h01 = (1.f - z)*n + z*h01;
        r = fsig(fmaf(xt1, wxr0, bxr0) + aR[2] + bhr0);
        z = fsig(fmaf(xt1, wxz0, bxz0) + aZ[2] + bhz0);
        n = ftanh(fmaf(xt1, wxn0, bxn0) + r*(aN[2] + bhn0));
        h10 = (1.f - z)*n + z*h10;
        r = fsig(fmaf(xt1, wxr1, bxr1) + aR[3] + bhr1);
        z = fsig(fmaf(xt1, wxz1, bxz1) + aZ[3] + bhz1);
        n = ftanh(fmaf(xt1, wxn1, bxn1) + r*(aN[3] + bhn1));
        h11 = (1.f - z)*n + z*h11;

        __nv_bfloat162 p0 = __floats2bfloat162_rn(h00, h01);
        float e0 = __bfloat162float(__low2bfloat16(p0));
        float e1 = __bfloat162float(__high2bfloat16(p0));
        __nv_bfloat162 q0 = __floats2bfloat162_rn(h00 - e0, h01 - e1);
        __nv_bfloat162 p1 = __floats2bfloat162_rn(h10, h11);
        float e2 = __bfloat162float(__low2bfloat16(p1));
        float e3 = __bfloat162float(__high2bfloat16(p1));
        __nv_bfloat162 q1 = __floats2bfloat162_rn(h10 - e2, h11 - e3);
        uint32_t o0 = (uint32_t)(nxt*1280 + gid*80 + u0*2);
        uint32_t o1 = (uint32_t)(nxt*1280 + (gid+8)*80 + u0*2);
        asm volatile("st.shared.b32 [%0], %1;" :: "r"(sHhW + o0), "r"(*(uint32_t*)&p0) : "memory");
        asm volatile("st.shared.b32 [%0], %1;" :: "r"(sHlW + o0), "r"(*(uint32_t*)&q0) : "memory");
        asm volatile("st.shared.b32 [%0], %1;" :: "r"(sHhW + o1), "r"(*(uint32_t*)&p1) : "memory");
        asm volatile("st.shared.b32 [%0], %1;" :: "r"(sHlW + o1), "r"(*(uint32_t*)&q1) : "memory");
        __syncthreads();
    }

    *(float2*)&g_hT[(size_t)(seqBase + gid)*32 + u0]     = make_float2(h00, h01);
    *(float2*)&g_hT[(size_t)(seqBase + gid + 8)*32 + u0] = make_float2(h10, h11);
    sHf[gid*33 + u0] = h00;     sHf[gid*33 + u0 + 1] = h01;
    sHf[(gid+8)*33 + u0] = h10; sHf[(gid+8)*33 + u0 + 1] = h11;
    __syncthreads();
    if (tid < 16){
        float s = bv[0];
        for (int o = 0; o < 16; ++o){
            float ao = sb116[o];
            #pragma unroll
            for (int j = 0; j < 32; ++j) ao = fmaf(sHf[tid*33 + j], sW12[o*32 + j], ao);
            s = fmaf(felu(ao), sV16[o], s);
        }
        g_t[seqBase + tid] = s / fmaxf(fabsf(s)*45.254833995939045f, 1e-12f);
    }
}

// ---------------- 3+9) rownorm fused with node0 build ----------------
__global__ void k_rownorm(const float* __restrict__ WQw, const float* __restrict__ WQb,
                          const float* __restrict__ tenc_w, const float* __restrict__ tenc_b,
                          const float* __restrict__ senc_w, const float* __restrict__ senc_b,
                          const float* __restrict__ degree){
    __shared__ float sW[HSCD*HID];
    __shared__ float sb[HID];
    __shared__ float sG[1024];
    __shared__ float sk[32];
    __shared__ float senc[4*32];
    int b = blockIdx.x, tid = threadIdx.x;
    for (int i = tid; i < HSCD*HID; i += 256) sW[i] = WQw[i];
    if (tid < HID) sb[tid] = WQb[tid];
    for (int i = tid; i < 1024; i += 256) sG[i] = g_gram[b*1024+i];
    if (tid < 32) sk[tid] = g_ksum[b*32+tid];
    if (tid < 32){
        senc[tid] = senc_w[tid]; senc[32+tid] = senc_b[tid];
        senc[64+tid] = tenc_w[tid]; senc[96+tid] = tenc_b[tid];
    }
    __syncthreads();
    int m = blockIdx.y*256 + tid;
    const float* hp = &g_hSC[(size_t)(b*MM+m)*HSCD];
    float hc[HSCD];
    #pragma unroll
    for (int c = 0; c < HSCD; ++c) hc[c] = hp[c];
    float q[HID];
    #pragma unroll
    for (int h = 0; h < HID; ++h){
        float a = sb[h];
        #pragma unroll
        for (int c = 0; c < HSCD; ++c) a = fmaf(hc[c], sW[c*HID+h], a);
        q[h] = a;
    }
    float num = 0.f, den = 0.f;
    #pragma unroll
    for (int h = 0; h < HID; ++h) num = fmaf(q[h], sk[h], num);
    #pragma unroll
    for (int i = 0; i < HID; ++i){
        float tmp = 0.f;
        #pragma unroll
        for (int j = 0; j < HID; ++j) tmp = fmaf(sG[i*32+j], q[j], tmp);
        den = fmaf(q[i], tmp, den);
    }
    float rn = num / fmaxf(sqrtf(fmaxf(den, 0.f)), 1e-12f);
    float* np = &g_node0[(size_t)(b*MM+m)*DG];
    #pragma unroll
    for (int c = 0; c < HSCD; ++c) np[c] = hc[c];
    float dm = degree[m];
    #pragma unroll
    for (int h = 0; h < 32; ++h) np[16+h] = fmaf(dm, senc[h], senc[32+h]);
    #pragma unroll
    for (int h = 0; h < 32; ++h) np[48+h] = fmaf(rn, senc[64+h], senc[96+h]);
}

// ---------------- 6) c_gate ----------------
__global__ void k_cg_part(const float* __restrict__ Wb){
    __shared__ float ts[8*128];
    int jt = blockIdx.x, nc = blockIdx.y, tid = threadIdx.x;
    int n0 = nc*128;
    for (int idx = tid; idx < 1024; idx += 256){
        int bb = idx >> 7, nn = idx & 127;
        ts[idx] = g_t[bb*MM + n0 + nn];
    }
    __syncthreads();
    int j = jt*256 + tid;
    float acc[8] = {0,0,0,0,0,0,0,0};
    for (int nn = 0; nn < 128; ++nn){
        float w = Wb[(size_t)(n0+nn)*MM + j];
        #pragma unroll
        for (int bb = 0; bb < 8; ++bb) acc[bb] = fmaf(ts[bb*128+nn], w, acc[bb]);
    }
    #pragma unroll
    for (int bb = 0; bb < 8; ++bb) g_cgp[(size_t)(nc*8+bb)*MM + j] = acc[bb];
}

__global__ void k_cg_fin(const float* __restrict__ wb){
    int gid = blockIdx.x*256 + threadIdx.x;
    int b = gid >> 11, j = gid & 2047;
    float s = wb[0];
    #pragma unroll
    for (int nc = 0; nc < 16; ++nc) s += g_cgp[(size_t)(nc*8+b)*MM + j];
    float c = sigf(s);
    g_c[gid] = c;
    g_tc[gid] = g_t[gid]*(1.f - c);
}

// ---------------- 7) sparse spatial ----------------
__global__ void k_spatial(const float* __restrict__ d_gate, const float* __restrict__ adj_orig,
                          const float* __restrict__ degree){
    int tid = threadIdx.x, lane = tid & 31, wid = tid >> 5;
    int i = blockIdx.x*8 + wid;
    float di = degree[i];
    int cnt = 0;
    for (int j0 = 0; j0 < MM; j0 += 32){
        int j = j0 + lane;
        float a = adj_orig[(size_t)i*MM + j];
        bool nz = a > 0.f;
        unsigned mask = __ballot_sync(0xffffffffu, nz);
        if (nz){
            float v = a * sigf(d_gate[(size_t)i*MM + j]*di*degree[j]);
            int pos = cnt + __popc(mask & ((1u << lane) - 1u));
            if (pos < SPCAP){ g_spi[i*SPCAP+pos] = j; g_spv[i*SPCAP+pos] = v; }
        }
        cnt += __popc(mask);
    }
    if (lane == 0) g_spc[i] = min(cnt, SPCAP);
}

// ---------------- 8) degree counts ----------------
__global__ void k_deg(const float* __restrict__ adj_geo){
    __shared__ float cs[8*512];
    __shared__ float tcs[8*512];
    int tid = threadIdx.x, lane = tid & 31, w = tid >> 5;
    int i = blockIdx.x*8 + w;
    int cnt[8] = {0,0,0,0,0,0,0,0};
    for (int j0 = 0; j0 < MM; j0 += 512){
        __syncthreads();
        for (int idx = tid; idx < 4096; idx += 256){
            int bb = idx >> 9, jj = idx & 511;
            cs[idx]  = g_c[bb*MM + j0 + jj];
            tcs[idx] = g_tc[bb*MM + j0 + jj];
        }
        __syncthreads();
        for (int j = lane; j < 512; j += 32){
            float ag = adj_geo[(size_t)i*MM + j0 + j];
            #pragma unroll
            for (int bb = 0; bb < 8; ++bb){
                float dyn = fmaf(ag, cs[bb*512+j], tcs[bb*512+j]);
                cnt[bb] += (dyn > 0.f);
            }
        }
    }
    int sc = g_spc[i];
    for (int s = lane; s < sc; s += 32){
        int j = g_spi[i*SPCAP+s]; float v = g_spv[i*SPCAP+s];
        float ag = adj_geo[(size_t)i*MM + j];
        #pragma unroll
        for (int bb = 0; bb < 8; ++bb){
            float dyn = fmaf(ag, g_c[bb*MM+j], g_tc[bb*MM+j]);
            if (dyn <= 0.f && dyn + v > 0.f) cnt[bb]++;
        }
    }
    #pragma unroll
    for (int bb = 0; bb < 8; ++bb){
        int vv = cnt[bb];
        #pragma unroll
        for (int o = 16; o; o >>= 1) vv += __shfl_down_sync(0xffffffffu, vv, o);
        if (lane == 0) g_dinv[bb*MM + i] = (vv > 0) ? 1.f/(float)vv : 0.f;
    }
}

// ---------------- adj -> bf16 hi/lo (once) ----------------
__global__ void k_adjcvt(const float* __restrict__ adj){
    size_t idx = (size_t)blockIdx.x*256 + threadIdx.x;
    float2 v = ((const float2*)adj)[idx];
    __nv_bfloat162 h2 = __floats2bfloat162_rn(v.x, v.y);
    float hx = __bfloat162float(__low2bfloat16(h2));
    float hy = __bfloat162float(__high2bfloat16(h2));
    __nv_bfloat162 l2 = __floats2bfloat162_rn(v.x - hx, v.y - hy);
    *(__nv_bfloat162*)&g_adjh[idx*2] = h2;
    *(__nv_bfloat162*)&g_adjl[idx*2] = l2;
}

// ---------------- B matrix build + u partials ----------------
__global__ void k_bmat(const float* __restrict__ node){
    __shared__ float sT[64*DG];
    __shared__ float su[DG];
    int j0 = blockIdx.x*64, b = blockIdx.y, tid = threadIdx.x;
    if (tid < DG) su[tid] = 0.f;
    __syncthreads();
    for (int idx = tid; idx < 64*DG; idx += 256){
        int j = idx/DG, d = idx%DG;
        float nv = node[(size_t)(b*MM + j0 + j)*DG + d];
        sT[idx] = g_c[b*MM + j0 + j] * nv;
        atomicAdd(&su[d], g_tc[b*MM + j0 + j] * nv);
    }
    __syncthreads();
    for (int idx = tid; idx < 64*DG; idx += 256){
        int d = idx >> 6, jj = idx & 63;
        float v = sT[jj*DG + d];
        __nv_bfloat16 h = __float2bfloat16(v);
        __nv_bfloat16 l = __float2bfloat16(v - __bfloat162float(h));
        size_t o = (size_t)(b*DG + d)*MM + j0 + jj;
        g_Bh[o] = h; g_Bl[o] = l;
    }
    if (tid < DG) g_upart[(b*32 + blockIdx.x)*DG + tid] = su[tid];
}

// ---------------- 11) fused GNN layer: mma.sync bf16 split, 512 threads ----------------
__global__ void __launch_bounds__(512,1) k_gemm(const float* __restrict__ nodeIn, float* __restrict__ nodeOut,
                       const float* __restrict__ gw, const float* __restrict__ gb){
    extern __shared__ char dsm[];
    __shared__ __align__(16) float sU[DG];
    __nv_bfloat16* sAh = (__nv_bfloat16*)dsm;
    __nv_bfloat16* sAl = (__nv_bfloat16*)(dsm + 18432);
    __nv_bfloat16* sBh = (__nv_bfloat16*)(dsm + 36864);
    __nv_bfloat16* sBl = (__nv_bfloat16*)(dsm + 48384);
    float* sY = (float*)dsm;
    float* sG = (float*)(dsm + 43008);

    int tid = threadIdx.x, lane = tid & 31, wid = tid >> 5;
    int i0 = blockIdx.x*128, b = blockIdx.y;
    int mBase = (wid >> 1)*16, nBase = (wid & 1)*40;
    int gid = lane >> 2, t2 = (lane & 3)*2;

    uint32_t aBase = smem_u32(sAh) + (uint32_t)((mBase + (lane & 15))*144 + (lane >> 4)*16);
    uint32_t bBase = smem_u32(sBh) + (uint32_t)((nBase + (lane & 7))*144 + ((lane >> 3) & 1)*16);

    if (tid < DG){
        float s = 0.f;
        #pragma unroll 8
        for (int p = 0; p < 32; ++p) s += g_upart[(b*32 + p)*DG + tid];
        sU[tid] = s;
    }

    int ra[2], sa[2];
    #pragma unroll
    for (int e = 0; e < 2; ++e){ int p = tid + e*512; ra[e] = p >> 3; sa[e] = (p & 7)*8; }
    int p1 = tid;
    int db0 = p1 >> 3, sb0 = (p1 & 7)*8;
    int p2 = tid + 512;
    int db1 = p2 >> 3, sb1v = (p2 & 7)*8;
    bool hasB1 = (p2 < 640);

    uint4 pAh[2], pAl[2], pBh0, pBl0, pBh1, pBl1;
    #pragma unroll
    for (int e = 0; e < 2; ++e){
        size_t o = (size_t)(i0 + ra[e])*MM + sa[e];
        pAh[e] = *(const uint4*)&g_adjh[o];
        pAl[e] = *(const uint4*)&g_adjl[o];
    }
    {
        size_t o = (size_t)(b*DG + db0)*MM + sb0;
        pBh0 = *(const uint4*)&g_Bh[o];
        pBl0 = *(const uint4*)&g_Bl[o];
        if (hasB1){
            size_t o1 = (size_t)(b*DG + db1)*MM + sb1v;
            pBh1 = *(const uint4*)&g_Bh[o1];
            pBl1 = *(const uint4*)&g_Bl[o1];
        }
    }

    float acc[5][4];
    #pragma unroll
    for (int n = 0; n < 5; ++n)
        #pragma unroll
        for (int k = 0; k < 4; ++k) acc[n][k] = 0.f;

    for (int jt = 0; jt < 32; ++jt){
        __syncthreads();
        #pragma unroll
        for (int e = 0; e < 2; ++e){
            *(uint4*)&sAh[ra[e]*72 + sa[e]] = pAh[e];
            *(uint4*)&sAl[ra[e]*72 + sa[e]] = pAl[e];
        }
        *(uint4*)&sBh[db0*72 + sb0] = pBh0;
        *(uint4*)&sBl[db0*72 + sb0] = pBl0;
        if (hasB1){
            *(uint4*)&sBh[db1*72 + sb1v] = pBh1;
            *(uint4*)&sBl[db1*72 + sb1v] = pBl1;
        }
        if (jt + 1 < 32){
            int j0 = (jt+1)*64;
            #pragma unroll
            for (int e = 0; e < 2; ++e){
                size_t o = (size_t)(i0 + ra[e])*MM + j0 + sa[e];
                pAh[e] = *(const uint4*)&g_adjh[o];
                pAl[e] = *(const uint4*)&g_adjl[o];
            }
            size_t o = (size_t)(b*DG + db0)*MM + j0 + sb0;
            pBh0 = *(const uint4*)&g_Bh[o];
            pBl0 = *(const uint4*)&g_Bl[o];
            if (hasB1){
                size_t o1 = (size_t)(b*DG + db1)*MM + j0 + sb1v;
                pBh1 = *(const uint4*)&g_Bh[o1];
                pBl1 = *(const uint4*)&g_Bl[o1];
            }
        }
        __syncthreads();
        #pragma unroll
        for (int ks = 0; ks < 4; ++ks){
            uint32_t aA = aBase + ks*32;
            uint32_t ah0, ah1, ah2, ah3, al0, al1, al2, al3;
            LDSM_X4(ah0, ah1, ah2, ah3, aA);
            LDSM_X4(al0, al1, al2, al3, aA + 18432);
            #pragma unroll
            for (int nt = 0; nt < 5; ++nt){
                uint32_t bA = bBase + nt*1152 + ks*32;
                uint32_t bh0, bh1, bl0, bl1;
                LDSM_X2(bh0, bh1, bA);
                LDSM_X2(bl0, bl1, bA + 11520);
                MMA16816(acc[nt], ah0, ah1, ah2, ah3, bh0, bh1);
                MMA16816(acc[nt], ah0, ah1, ah2, ah3, bl0, bl1);
                MMA16816(acc[nt], al0, al1, al2, al3, bh0, bh1);
            }
        }
    }
    __syncthreads();
    #pragma unroll
    for (int nt = 0; nt < 5; ++nt){
        int col = nBase + nt*8 + t2;
        sY[(mBase+gid)*84   + col]     = acc[nt][0];
        sY[(mBase+gid)*84   + col + 1] = acc[nt][1];
        sY[(mBase+gid+8)*84 + col]     = acc[nt][2];
        sY[(mBase+gid+8)*84 + col + 1] = acc[nt][3];
    }
    for (int idx = tid; idx < 6400; idx += 512)
        sG[(idx/80)*84 + idx%80] = gw[idx];
    __syncthreads();

    int q = tid & 3, ig = tid >> 2;
    {
        int row = ig;
        int i = i0 + row;
        float a20[20];
        float4* yp = (float4*)&sY[row*84 + q*20];
        #pragma unroll
        for (int v = 0; v < 5; ++v){
            float4 y4 = yp[v];
            a20[v*4+0] = y4.x; a20[v*4+1] = y4.y; a20[v*4+2] = y4.z; a20[v*4+3] = y4.w;
        }
        int sc = g_spc[i];
        for (int s = 0; s < sc; ++s){
            int j = g_spi[i*SPCAP+s]; float v = g_spv[i*SPCAP+s];
            const float4* np = (const float4*)&nodeIn[(size_t)(b*MM + j)*DG + q*20];
            #pragma unroll
            for (int vv = 0; vv < 5; ++vv){
                float4 n = np[vv];
                a20[vv*4+0] = fmaf(v, n.x, a20[vv*4+0]);
                a20[vv*4+1] = fmaf(v, n.y, a20[vv*4+1]);
                a20[vv*4+2] = fmaf(v, n.z, a20[vv*4+2]);
                a20[vv*4+3] = fmaf(v, n.w, a20[vv*4+3]);
            }
        }
        float dinv = g_dinv[b*MM + i];
        const float4* up = (const float4*)&sU[q*20];
        #pragma unroll
        for (int vv = 0; vv < 5; ++vv){
            float4 u4 = up[vv];
            float4 y;
            y.x = dinv*(a20[vv*4+0] + u4.x);
            y.y = dinv*(a20[vv*4+1] + u4.y);
            y.z = dinv*(a20[vv*4+2] + u4.z);
            y.w = dinv*(a20[vv*4+3] + u4.w);
            yp[vv] = y;
        }
    }
    __syncthreads();
    {
        int i = i0 + ig;
        unsigned long long z2[10];
        const float2* gb2 = (const float2*)&gb[q*20];
        #pragma unroll
        for (int k = 0; k < 10; ++k){ float2 g2 = gb2[k]; PACK2(z2[k], g2.x, g2.y); }
        for (int d = 0; d < 80; ++d){
            float yv = sY[ig*84 + d];
            unsigned long long py; PACKB(py, yv);
            const ulonglong2* gp = (const ulonglong2*)&sG[d*84 + q*20];
            #pragma unroll
            for (int v = 0; v < 5; ++v){
                ulonglong2 g2 = gp[v];
                FFMA2(z2[v*2],   py, g2.x);
                FFMA2(z2[v*2+1], py, g2.y);
            }
        }
        float* op = &nodeOut[(size_t)(b*MM + i)*DG + q*20];
        #pragma unroll
        for (int v = 0; v < 5; ++v){
            float4 o4;
            float za, zbv, zc, zd;
            UNPACK2(za, zbv, z2[v*2]);
            UNPACK2(zc, zd, z2[v*2+1]);
            o4.x = eluf(za); o4.y = eluf(zbv); o4.z = eluf(zc); o4.w = eluf(zd);
            *(float4*)&op[v*4] = o4;
        }
    }
}

// ---------------- 12) final projection (float4 rows) ----------------
__global__ void k_final(const float* __restrict__ out_w, const float* __restrict__ out_b,
                        float* __restrict__ out){
    __shared__ float sw[272];
    int tid = threadIdx.x;
    for (int i = tid; i < 272; i += 256) sw[i] = out_w[i];
    __syncthreads();
    int gid = blockIdx.x*256 + tid;
    float a = out_b[0];
    const float4* n0 = (const float4*)&g_node0[(size_t)gid*DG];
    const float4* n1 = (const float4*)&g_node1[(size_t)gid*DG];
    const float4* n2 = (const float4*)&g_node2[(size_t)gid*DG];
    const float4* ht = (const float4*)&g_hT[(size_t)gid*32];
    #pragma unroll
    for (int k = 0; k < 20; ++k){
        float4 v = n0[k];
        const float* w = &sw[k*4];
        a = fmaf(v.x, w[0], a); a = fmaf(v.y, w[1], a);
        a = fmaf(v.z, w[2], a); a = fmaf(v.w, w[3], a);
    }
    #pragma unroll
    for (int k = 0; k < 20; ++k){
        float4 v = n1[k];
        const float* w = &sw[80 + k*4];
        a = fmaf(v.x, w[0], a); a = fmaf(v.y, w[1], a);
        a = fmaf(v.z, w[2], a); a = fmaf(v.w, w[3], a);
    }
    #pragma unroll
    for (int k = 0; k < 20; ++k){
        float4 v = n2[k];
        const float* w = &sw[160 + k*4];
        a = fmaf(v.x, w[0], a); a = fmaf(v.y, w[1], a);
        a = fmaf(v.z, w[2], a); a = fmaf(v.w, w[3], a);
    }
    #pragma unroll
    for (int k = 0; k < 8; ++k){
        float4 v = ht[k];
        const float* w = &sw[240 + k*4];
        a = fmaf(v.x, w[0], a); a = fmaf(v.y, w[1], a);
        a = fmaf(v.z, w[2], a); a = fmaf(v.w, w[3], a);
    }
    out[gid] = a;
}

// ---------------- launch ----------------
extern "C" void kernel_launch(void* const* d_in, const int* in_sizes, int n_in,
                              void* d_out, int out_size){
    const float* x       = (const float*)d_in[0];
    const float* Wt      = (const float*)d_in[1];
    const float* bt      = (const float*)d_in[2];
    const float* WQ_w    = (const float*)d_in[3];
    const float* WQ_b    = (const float*)d_in[4];
    const float* WK_w    = (const float*)d_in[5];
    const float* WK_b    = (const float*)d_in[6];
    const float* tenc_w  = (const float*)d_in[7];
    const float* tenc_b  = (const float*)d_in[8];
    const float* senc_w  = (const float*)d_in[9];
    const float* senc_b  = (const float*)d_in[10];
    const float* gru_wih = (const float*)d_in[11];
    const float* gru_whh = (const float*)d_in[12];
    const float* gru_bih = (const float*)d_in[13];
    const float* gru_bhh = (const float*)d_in[14];
    const float* V       = (const float*)d_in[15];
    const float* bv      = (const float*)d_in[16];
    const float* W1      = (const float*)d_in[17];
    const float* b1      = (const float*)d_in[18];
    const float* W2      = (const float*)d_in[19];
    const float* Wb      = (const float*)d_in[20];
    const float* wb      = (const float*)d_in[21];
    const float* d_gate  = (const float*)d_in[22];
    const float* adj_geo = (const float*)d_in[23];
    const float* adj_orig= (const float*)d_in[24];
    const float* degree  = (const float*)d_in[25];
    const float* gnn_w   = (const float*)d_in[26];
    const float* gnn_b   = (const float*)d_in[27];
    const float* out_w   = (const float*)d_in[28];
    const float* out_b   = (const float*)d_in[29];
    float* out = (float*)d_out;

    const int GEMM_SMEM = 69888;
    cudaFuncSetAttribute(k_gemm, cudaFuncAttributeMaxDynamicSharedMemorySize, GEMM_SMEM);

    float *n0, *n1, *n2;
    cudaGetSymbolAddress((void**)&n0, g_node0);
    cudaGetSymbolAddress((void**)&n1, g_node1);
    cudaGetSymbolAddress((void**)&n2, g_node2);

    k_adjcvt<<<MM*MM/2/256, 256>>>(adj_geo);
    k_hsc<<<dim3(BB, MM/256), 256>>>(x, Wt, bt);
    k_kstats<<<dim3(BB, 8), 256>>>(WK_w, WK_b);
    k_gru<<<BB*MM/16, 128>>>(x, gru_wih, gru_whh, gru_bih, gru_bhh,
                             W1, W2, b1, V, bv);                     // profiled slot
    k_kreduce<<<BB, 256>>>();
    k_rownorm<<<dim3(BB, MM/256), 256>>>(WQ_w, WQ_b, tenc_w, tenc_b,
                                         senc_w, senc_b, degree);
    k_cg_part<<<dim3(8, 16), 256>>>(Wb);
    k_cg_fin<<<BB*MM/256, 256>>>(wb);
    k_spatial<<<MM/8, 256>>>(d_gate, adj_orig, degree);
    k_deg<<<MM/8, 256>>>(adj_geo);
    k_bmat<<<dim3(MM/64, BB), 256>>>(n0);
    k_gemm<<<dim3(MM/128, BB), 512, GEMM_SMEM>>>(n0, n1, gnn_w, gnn_b);
    k_bmat<<<dim3(MM/64, BB), 256>>>(n1);
    k_gemm<<<dim3(MM/128, BB), 512, GEMM_SMEM>>>(n1, n2, gnn_w + 6400, gnn_b + 80);
    k_final<<<BB*MM/256, 256>>>(out_w, out_b, out);
}